// round 1
// baseline (speedup 1.0000x reference)
#include <cuda_runtime.h>

// ---------------- problem constants ----------------
#define BB 4
#define Cch 256
#define THW 3136          // 16*14*14 per channel
#define HWs 196
#define DEMO_TOK 784      // 4*196
#define OBS_TOK 2352      // 12*196
#define CATN 980          // 784 + 196
#define Ff 256
#define CHh 32
#define OBS_Tn 12
#define INV_TEMP 0.0625f  // 1/sqrt(256)
#define EPSV 1e-5f
#define CTHW (Cch*THW)    // 802816

// ---------------- scratch (device globals; allocation-free) ----------------
__device__ __align__(256) float g_x[BB*CTHW];                 // working tensor
__device__ __align__(256) float g_dq[BB*Ff*DEMO_TOK];
__device__ __align__(256) float g_dk[BB*Ff*DEMO_TOK];
__device__ __align__(256) float g_dv[BB*Ff*DEMO_TOK];
__device__ __align__(256) float g_dvatt[BB*Ff*DEMO_TOK];
__device__ __align__(256) float g_oq[BB*Ff*OBS_TOK];
__device__ __align__(256) float g_ok[BB*Ff*OBS_TOK];
__device__ __align__(256) float g_ov[BB*Ff*OBS_TOK];
__device__ __align__(256) float g_mg[BB*Ff*OBS_TOK];
__device__ __align__(256) float g_S [32u*DEMO_TOK*DEMO_TOK];  // demo attn probs
__device__ __align__(256) float g_S2[384u*CATN*HWs];          // obs attn probs
__device__ float g_mean[Cch];
__device__ float g_istd[Cch];

// ---------------- copy input -> g_x ----------------
__global__ void k_copy(const float4* __restrict__ src) {
    int e = blockIdx.x * 256 + threadIdx.x;   // 3136*256 = 802816 float4 exactly
    ((float4*)g_x)[e] = src[e];
}

// ---------------- generic 1x1-conv GEMM: O = W(256x256) * X(256xN) ----------------
// X element (k,n) at X[b*xbstr + k*ldx + xoff + n]; O element (m,n) at
// O[b*obstr + m*ldo + ooff + n]. fuse=1: O = O + relu(acc) (residual in place).
__global__ void k_conv(const float* __restrict__ W, const float* __restrict__ X,
                       int ldx, int xoff, long xbstr,
                       float* __restrict__ O, int ldo, int ooff, long obstr,
                       int N, int fuse)
{
    __shared__ float As[16][68];
    __shared__ float Bs[16][68];
    const int t  = threadIdx.x;
    const int b  = blockIdx.z;
    const int m0 = blockIdx.y * 64;
    const int n0 = blockIdx.x * 64;
    const int ty = t >> 4, tx = t & 15;
    const float* Xb = X + b * xbstr + xoff;
    float acc[4][4];
#pragma unroll
    for (int i = 0; i < 4; i++)
#pragma unroll
        for (int j = 0; j < 4; j++) acc[i][j] = 0.f;

    for (int k0 = 0; k0 < 256; k0 += 16) {
        for (int i = t; i < 1024; i += 256) {
            int m = i >> 4, k = i & 15;
            As[k][m] = W[(m0 + m) * 256 + k0 + k];
        }
        for (int i = t; i < 1024; i += 256) {
            int k = i >> 6, n = i & 63;
            int nn = n0 + n;
            Bs[k][n] = (nn < N) ? Xb[(long)(k0 + k) * ldx + nn] : 0.f;
        }
        __syncthreads();
#pragma unroll
        for (int k = 0; k < 16; k++) {
            float4 ra = *(const float4*)&As[k][ty * 4];
            float4 rb = *(const float4*)&Bs[k][tx * 4];
            float a[4] = {ra.x, ra.y, ra.z, ra.w};
            float bv[4] = {rb.x, rb.y, rb.z, rb.w};
#pragma unroll
            for (int i = 0; i < 4; i++)
#pragma unroll
                for (int j = 0; j < 4; j++) acc[i][j] += a[i] * bv[j];
        }
        __syncthreads();
    }
    float* Ob = O + b * obstr + ooff;
#pragma unroll
    for (int i = 0; i < 4; i++) {
        int m = m0 + ty * 4 + i;
#pragma unroll
        for (int j = 0; j < 4; j++) {
            int n = n0 + tx * 4 + j;
            if (n < N) {
                float* p = Ob + (long)m * ldo + n;
                if (fuse) *p = *p + fmaxf(acc[i][j], 0.f);
                else      *p = acc[i][j];
            }
        }
    }
}

// ---------------- demo attention: scores + softmax (over j) -> g_S ----------------
// per (b,h): S[i,j] = softmax_j( (1/16) sum_c dk[c,i]*dq[c,j] ), i,j in [0,784)
// block: 16 rows i x 784 j; 256 thr: r=t>>4 (row), g=t&15 (49 j's each)
__global__ void k_demo_attn() {
    const int t = threadIdx.x;
    const int itile = blockIdx.x;        // 0..48
    const int bh = blockIdx.y;           // 0..31
    const int b = bh >> 3, h = bh & 7;
    const float* Kp = g_dk + ((long)b * Ff + h * CHh) * DEMO_TOK;
    const float* Qp = g_dq + ((long)b * Ff + h * CHh) * DEMO_TOK;
    float* Pout = g_S + (long)bh * DEMO_TOK * DEMO_TOK;
    __shared__ float Ks[32][16];
    __shared__ float Qs[8][16][52];      // padded groups of 49 for aligned float4
    const int r = t >> 4, g = t & 15;
    float acc[49];
#pragma unroll
    for (int jj = 0; jj < 49; jj++) acc[jj] = 0.f;

    for (int e = t; e < 512; e += 256) {
        int c = e >> 4, ii = e & 15;
        Ks[c][ii] = Kp[(long)c * DEMO_TOK + itile * 16 + ii];
    }
    for (int cb = 0; cb < 4; cb++) {
        __syncthreads();
        for (int e = t; e < 8 * 784; e += 256) {
            int c = e / 784, j = e - c * 784;
            Qs[c][j / 49][j % 49] = Qp[(long)(cb * 8 + c) * DEMO_TOK + j];
        }
        __syncthreads();
#pragma unroll
        for (int cc = 0; cc < 8; cc++) {
            float a = Ks[cb * 8 + cc][r];
            const float* q = Qs[cc][g];
#pragma unroll
            for (int v = 0; v < 12; v++) {
                float4 qq = *(const float4*)(q + v * 4);
                acc[v*4+0] += a * qq.x; acc[v*4+1] += a * qq.y;
                acc[v*4+2] += a * qq.z; acc[v*4+3] += a * qq.w;
            }
            acc[48] += a * q[48];
        }
    }
    float mx = -1e30f;
#pragma unroll
    for (int jj = 0; jj < 49; jj++) { acc[jj] *= INV_TEMP; mx = fmaxf(mx, acc[jj]); }
#pragma unroll
    for (int o = 8; o; o >>= 1) mx = fmaxf(mx, __shfl_xor_sync(0xffffffffu, mx, o));
    float sm = 0.f;
#pragma unroll
    for (int jj = 0; jj < 49; jj++) { float p = __expf(acc[jj] - mx); acc[jj] = p; sm += p; }
#pragma unroll
    for (int o = 8; o; o >>= 1) sm += __shfl_xor_sync(0xffffffffu, sm, o);
    float inv = 1.f / sm;
    const int i = itile * 16 + r;
    float* op = Pout + (long)i * DEMO_TOK + g * 49;
#pragma unroll
    for (int jj = 0; jj < 49; jj++) op[jj] = acc[jj] * inv;
}

// ---------------- demo AV: dv_att[c,i] = sum_j dv[c,j] * P[i,j] ----------------
// block: 196 output columns i; 32 c accumulators per thread; K=784 in tiles of 28
__global__ void k_demo_av() {
    const int t = threadIdx.x;           // 0..195
    const int iq = blockIdx.x;           // 0..3
    const int bh = blockIdx.y;           // 0..31
    const int b = bh >> 3, h = bh & 7;
    __shared__ float Vt[32][28];
    __shared__ float Pt[196][28];
    const float* Vp = g_dv + ((long)b * Ff + h * CHh) * DEMO_TOK;
    const float* Pp = g_S + (long)bh * DEMO_TOK * DEMO_TOK;
    float acc[32];
#pragma unroll
    for (int c = 0; c < 32; c++) acc[c] = 0.f;

    for (int jt = 0; jt < 28; jt++) {
        int j0 = jt * 28;
        __syncthreads();
        for (int e = t; e < 896; e += 196) {
            int c = e / 28, kk = e - c * 28;
            Vt[c][kk] = Vp[(long)c * DEMO_TOK + j0 + kk];
        }
        for (int e = t; e < 5488; e += 196) {
            int rr = e / 28, kk = e - rr * 28;
            Pt[rr][kk] = Pp[(long)(iq * 196 + rr) * DEMO_TOK + j0 + kk];
        }
        __syncthreads();
#pragma unroll
        for (int k4 = 0; k4 < 7; k4++) {
            float4 p = *(const float4*)&Pt[t][k4 * 4];
#pragma unroll
            for (int c = 0; c < 32; c++) {
                float4 v = *(const float4*)&Vt[c][k4 * 4];
                acc[c] += v.x * p.x + v.y * p.y + v.z * p.z + v.w * p.w;
            }
        }
    }
    float* op = g_dvatt + ((long)b * Ff + h * CHh) * DEMO_TOK + iq * 196 + t;
#pragma unroll
    for (int c = 0; c < 32; c++) op[(long)c * DEMO_TOK] = acc[c];
}

// ---------------- obs attention: scores + softmax (over j in 196) -> g_S2 ----------------
// per (b,t,h): S2[i,j] = softmax_j( (1/16) sum_c catk[c,i]*oq[c,j] ), i<980, j<196
// block: 64 rows i x 196 j; thread r=t>>2, g=t&3 (49 j's), quad shfl for softmax
__global__ void k_obs_attn() {
    const int t = threadIdx.x;
    const int itile = blockIdx.x;        // 0..15
    const int z = blockIdx.y;            // 0..383  = b*96 + tt*8 + h
    const int b = z / 96, tt = (z / 8) % 12, h = z & 7;
    __shared__ float Ks[32][64];
    __shared__ float Qs[32][4][52];
    const float* Kdp = g_dk + ((long)b * Ff + h * CHh) * DEMO_TOK;
    const float* Kop = g_ok + ((long)b * Ff + h * CHh) * OBS_TOK + tt * HWs;
    const float* Qp  = g_oq + ((long)b * Ff + h * CHh) * OBS_TOK + tt * HWs;
    float* Pout = g_S2 + (long)z * CATN * HWs;
    const int r = t >> 2, g = t & 3;

    for (int e = t; e < 2048; e += 256) {
        int c = e >> 6, ii = e & 63;
        int i = itile * 64 + ii;
        float v = 0.f;
        if (i < DEMO_TOK)   v = Kdp[(long)c * DEMO_TOK + i];
        else if (i < CATN)  v = Kop[(long)c * OBS_TOK + (i - DEMO_TOK)];
        Ks[c][ii] = v;
    }
    for (int e = t; e < 32 * 196; e += 256) {
        int c = e / 196, j = e - c * 196;
        Qs[c][j / 49][j % 49] = Qp[(long)c * OBS_TOK + j];
    }
    __syncthreads();
    float acc[49];
#pragma unroll
    for (int jj = 0; jj < 49; jj++) acc[jj] = 0.f;
#pragma unroll
    for (int c = 0; c < 32; c++) {
        float a = Ks[c][r];
        const float* q = Qs[c][g];
#pragma unroll
        for (int v = 0; v < 12; v++) {
            float4 qq = *(const float4*)(q + v * 4);
            acc[v*4+0] += a * qq.x; acc[v*4+1] += a * qq.y;
            acc[v*4+2] += a * qq.z; acc[v*4+3] += a * qq.w;
        }
        acc[48] += a * q[48];
    }
    float mx = -1e30f;
#pragma unroll
    for (int jj = 0; jj < 49; jj++) { acc[jj] *= INV_TEMP; mx = fmaxf(mx, acc[jj]); }
    mx = fmaxf(mx, __shfl_xor_sync(0xffffffffu, mx, 1));
    mx = fmaxf(mx, __shfl_xor_sync(0xffffffffu, mx, 2));
    float sm = 0.f;
#pragma unroll
    for (int jj = 0; jj < 49; jj++) { float p = __expf(acc[jj] - mx); acc[jj] = p; sm += p; }
    sm += __shfl_xor_sync(0xffffffffu, sm, 1);
    sm += __shfl_xor_sync(0xffffffffu, sm, 2);
    float inv = 1.f / sm;
    const int i = itile * 64 + r;
    if (i < CATN) {
        float* op = Pout + (long)i * HWs + g * 49;
#pragma unroll
        for (int jj = 0; jj < 49; jj++) op[jj] = acc[jj] * inv;
    }
}

// ---------------- obs AV: merged[c,j] = sum_k catv[c,k]*P2[k,j] -> g_mg ----------------
// per (b,t,h): 196 output columns j per thread, 32 c accumulators, K=980 tiles of 28
__global__ void k_obs_av() {
    const int z = blockIdx.x;            // 0..383
    const int b = z / 96, tt = (z / 8) % 12, h = z & 7;
    const int t = threadIdx.x;           // 0..195
    __shared__ float Vt[32][28];
    __shared__ float Pt[28][196];
    const float* Vdp = g_dvatt + ((long)b * Ff + h * CHh) * DEMO_TOK;
    const float* Vop = g_ov    + ((long)b * Ff + h * CHh) * OBS_TOK + tt * HWs;
    const float* Pp  = g_S2 + (long)z * CATN * HWs;
    float acc[32];
#pragma unroll
    for (int c = 0; c < 32; c++) acc[c] = 0.f;

    for (int kt = 0; kt < 35; kt++) {
        int k0 = kt * 28;
        __syncthreads();
        for (int e = t; e < 896; e += 196) {
            int c = e / 28, kk = e - c * 28;
            int k = k0 + kk;
            Vt[c][kk] = (k < DEMO_TOK) ? Vdp[(long)c * DEMO_TOK + k]
                                       : Vop[(long)c * OBS_TOK + (k - DEMO_TOK)];
        }
        for (int it = 0; it < 28; it++)
            Pt[it][t] = Pp[(long)(k0 + it) * HWs + t];
        __syncthreads();
#pragma unroll
        for (int k4 = 0; k4 < 7; k4++) {
            float p0 = Pt[k4*4+0][t], p1 = Pt[k4*4+1][t];
            float p2 = Pt[k4*4+2][t], p3 = Pt[k4*4+3][t];
#pragma unroll
            for (int c = 0; c < 32; c++) {
                float4 v = *(const float4*)&Vt[c][k4 * 4];
                acc[c] += v.x * p0 + v.y * p1 + v.z * p2 + v.w * p3;
            }
        }
    }
    float* op = g_mg + ((long)b * Ff + h * CHh) * OBS_TOK + tt * HWs + t;
#pragma unroll
    for (int c = 0; c < 32; c++) op[(long)c * OBS_TOK] = acc[c];
}

// ---------------- BatchNorm stats: per channel over (B,T,H,W) ----------------
__global__ void k_bnstats() {
    const int c = blockIdx.x;
    float s = 0.f, s2 = 0.f;
    for (int e = threadIdx.x; e < BB * THW; e += 256) {
        int b = e / THW, k = e - b * THW;
        float v = g_x[(long)b * CTHW + (long)c * THW + k];
        s += v; s2 += v * v;
    }
#pragma unroll
    for (int o = 16; o; o >>= 1) {
        s  += __shfl_xor_sync(0xffffffffu, s, o);
        s2 += __shfl_xor_sync(0xffffffffu, s2, o);
    }
    __shared__ float ws[8], ws2[8];
    int w = threadIdx.x >> 5;
    if ((threadIdx.x & 31) == 0) { ws[w] = s; ws2[w] = s2; }
    __syncthreads();
    if (threadIdx.x == 0) {
        float S = 0.f, S2 = 0.f;
#pragma unroll
        for (int i = 0; i < 8; i++) { S += ws[i]; S2 += ws2[i]; }
        float m = S * (1.f / 12544.f);
        float var = S2 * (1.f / 12544.f) - m * m;
        g_mean[c] = m;
        g_istd[c] = rsqrtf(var + EPSV);
    }
}

// ---------------- BatchNorm apply (fused affine), vectorized ----------------
__global__ void k_bnapply(const float* __restrict__ gamma, const float* __restrict__ beta,
                          float* __restrict__ out) {
    int e = blockIdx.x * 256 + threadIdx.x;   // 802816 float4
    int c = (e / 784) & 255;                  // 784 float4 per channel-slab
    float4 v = ((const float4*)g_x)[e];
    float a = gamma[c] * g_istd[c];
    float b2 = beta[c] - g_mean[c] * a;
    v.x = v.x * a + b2; v.y = v.y * a + b2; v.z = v.z * a + b2; v.w = v.w * a + b2;
    ((float4*)out)[e] = v;
}

// ---------------- host orchestration ----------------
extern "C" void kernel_launch(void* const* d_in, const int* in_sizes, int n_in,
                              void* d_out, int out_size) {
    const float* x    = (const float*)d_in[0];
    const float* w_dq = (const float*)d_in[1];
    const float* w_dk = (const float*)d_in[2];
    const float* w_dv = (const float*)d_in[3];
    const float* w_oq = (const float*)d_in[4];
    const float* w_ok = (const float*)d_in[5];
    const float* w_ov = (const float*)d_in[6];
    const float* w_oo = (const float*)d_in[7];
    const float* gam  = (const float*)d_in[8];
    const float* bet  = (const float*)d_in[9];
    float* out = (float*)d_out;

    float *p_x, *p_dq, *p_dk, *p_dv, *p_oq, *p_ok, *p_ov, *p_mg;
    cudaGetSymbolAddress((void**)&p_x,  g_x);
    cudaGetSymbolAddress((void**)&p_dq, g_dq);
    cudaGetSymbolAddress((void**)&p_dk, g_dk);
    cudaGetSymbolAddress((void**)&p_dv, g_dv);
    cudaGetSymbolAddress((void**)&p_oq, g_oq);
    cudaGetSymbolAddress((void**)&p_ok, g_ok);
    cudaGetSymbolAddress((void**)&p_ov, g_ov);
    cudaGetSymbolAddress((void**)&p_mg, g_mg);

    k_copy<<<3136, 256>>>((const float4*)x);

    const long xbs = (long)Cch * THW;    // 802816
    const long dbs = (long)Ff * DEMO_TOK;
    const long obs = (long)Ff * OBS_TOK;
    dim3 cgd(13, 4, BB), cgo(37, 4, BB);

    for (int l = 0; l < 3; l++) {
        const int WO = l * Ff * Cch;
        // demo q/k/v convs (read g_x demo region)
        k_conv<<<cgd, 256>>>(w_dq + WO, p_x, THW, 0, xbs, p_dq, DEMO_TOK, 0, dbs, DEMO_TOK, 0);
        k_conv<<<cgd, 256>>>(w_dk + WO, p_x, THW, 0, xbs, p_dk, DEMO_TOK, 0, dbs, DEMO_TOK, 0);
        k_conv<<<cgd, 256>>>(w_dv + WO, p_x, THW, 0, xbs, p_dv, DEMO_TOK, 0, dbs, DEMO_TOK, 0);
        // obs q/k/v convs (read g_x obs region, offset 784)
        k_conv<<<cgo, 256>>>(w_oq + WO, p_x, THW, DEMO_TOK, xbs, p_oq, OBS_TOK, 0, obs, OBS_TOK, 0);
        k_conv<<<cgo, 256>>>(w_ok + WO, p_x, THW, DEMO_TOK, xbs, p_ok, OBS_TOK, 0, obs, OBS_TOK, 0);
        k_conv<<<cgo, 256>>>(w_ov + WO, p_x, THW, DEMO_TOK, xbs, p_ov, OBS_TOK, 0, obs, OBS_TOK, 0);
        // demo attention
        k_demo_attn<<<dim3(49, 32), 256>>>();
        k_demo_av<<<dim3(4, 32), 196>>>();
        // obs attention
        k_obs_attn<<<dim3(16, 384), 256>>>();
        k_obs_av<<<384, 196>>>();
        // output conv + relu + residual (in place into g_x obs region)
        k_conv<<<cgo, 256>>>(w_oo + WO, p_mg, OBS_TOK, 0, obs, p_x, THW, DEMO_TOK, xbs, OBS_TOK, 1);
        // batchnorm
        k_bnstats<<<256, 256>>>();
        k_bnapply<<<3136, 256>>>(gam + l * Cch, bet + l * Cch, (l == 2) ? out : p_x);
    }
}

// round 3
// speedup vs baseline: 1.5647x; 1.5647x over previous
#include <cuda_runtime.h>

// ---------------- problem constants ----------------
#define BB 4
#define THW 3136          // 16*14*14
#define DEMO_TOK 784
#define OBS_TOK 2352
#define INV_TEMP 0.0625f  // 1/sqrt(256)
#define EPSV 1e-5f
#define CTHW (256*THW)    // 802816

// ---------------- scratch (device globals; allocation-free) ----------------
__device__ __align__(256) float g_x[BB*CTHW];
__device__ __align__(256) float g_dq[BB*256*DEMO_TOK];
__device__ __align__(256) float g_dk[BB*256*DEMO_TOK];
__device__ __align__(256) float g_dv[BB*256*DEMO_TOK];
__device__ __align__(256) float g_dvatt[BB*256*DEMO_TOK];
__device__ __align__(256) float g_oq[BB*256*OBS_TOK];
__device__ __align__(256) float g_ok[BB*256*OBS_TOK];
__device__ __align__(256) float g_ov[BB*256*OBS_TOK];
__device__ __align__(256) float g_mg[BB*256*OBS_TOK];
__device__ __align__(256) float g_part[2*384*32*196];   // obs AV partials (k-split)
__device__ float g_mean[256];
__device__ float g_istd[256];

// ---------------- copy input -> g_x ----------------
// total = BB*CTHW = 3,211,264 floats = 802,816 float4 -> 3136 blocks x 256 thr
__global__ void k_copy(const float4* __restrict__ src) {
    int e = blockIdx.x * 256 + threadIdx.x;
    ((float4*)g_x)[e] = src[e];
}

// ---------------- fused triple 1x1-conv GEMM ----------------
// grid.y: 12 tiles (qkv) or 4 tiles (single W). sel = my>>2 picks W/O.
// O = W(256x256) * X(256xN); fuse=1: O += relu(acc)
__global__ __launch_bounds__(256) void k_conv3(
    const float* __restrict__ W0, const float* __restrict__ W1, const float* __restrict__ W2,
    const float* __restrict__ X, int ldx, int xoff, long xbstr,
    float* __restrict__ O0, float* __restrict__ O1, float* __restrict__ O2,
    int ldo, int ooff, long obstr, int N, int fuse)
{
    __shared__ float As[32][68];
    __shared__ float Bs[32][68];
    const int t  = threadIdx.x;
    const int b  = blockIdx.z;
    const int my = blockIdx.y;
    const int sel = my >> 2;
    const int m0  = (my & 3) * 64;
    const int n0  = blockIdx.x * 64;
    const float* W = (sel == 0) ? W0 : ((sel == 1) ? W1 : W2);
    float* Obase   = (sel == 0) ? O0 : ((sel == 1) ? O1 : O2);
    const float* Xb = X + b * xbstr + xoff;
    const int ty = t >> 4, tx = t & 15;
    float acc[4][4];
#pragma unroll
    for (int i = 0; i < 4; i++)
#pragma unroll
        for (int j = 0; j < 4; j++) acc[i][j] = 0.f;

    for (int k0 = 0; k0 < 256; k0 += 32) {
        // A: 64 m x 32 k, float4 along k, store transposed As[k][m]
#pragma unroll
        for (int e = t; e < 512; e += 256) {
            int m = e >> 3, k4 = e & 7;
            float4 w4 = *(const float4*)&W[(m0 + m) * 256 + k0 + k4 * 4];
            As[k4*4+0][m] = w4.x; As[k4*4+1][m] = w4.y;
            As[k4*4+2][m] = w4.z; As[k4*4+3][m] = w4.w;
        }
        // B: 32 k x 64 n, float4 along n (N % 4 == 0 always here)
#pragma unroll
        for (int e = t; e < 512; e += 256) {
            int k = e >> 4, n4 = e & 15;
            float4 x4 = make_float4(0.f, 0.f, 0.f, 0.f);
            if (n0 + n4 * 4 < N)
                x4 = *(const float4*)&Xb[(long)(k0 + k) * ldx + n0 + n4 * 4];
            *(float4*)&Bs[k][n4 * 4] = x4;
        }
        __syncthreads();
#pragma unroll
        for (int k = 0; k < 32; k++) {
            float4 ra = *(const float4*)&As[k][ty * 4];
            float4 rb = *(const float4*)&Bs[k][tx * 4];
            float a[4] = {ra.x, ra.y, ra.z, ra.w};
            float bv[4] = {rb.x, rb.y, rb.z, rb.w};
#pragma unroll
            for (int i = 0; i < 4; i++)
#pragma unroll
                for (int j = 0; j < 4; j++) acc[i][j] += a[i] * bv[j];
        }
        __syncthreads();
    }
    float* Ob = Obase + b * obstr + ooff;
#pragma unroll
    for (int i = 0; i < 4; i++) {
        int m = m0 + ty * 4 + i;
#pragma unroll
        for (int j = 0; j < 4; j++) {
            int n = n0 + tx * 4 + j;
            if (n < N) {
                float* p = Ob + (long)m * ldo + n;
                if (fuse) *p = *p + fmaxf(acc[i][j], 0.f);
                else      *p = acc[i][j];
            }
        }
    }
}

// ---------------- fused demo attention: scores + softmax + AV ----------------
// block: (itile in 49) x (bh in 32); 16 rows i per block, 256 threads.
// out[c,i] = sum_j dv[c,j] * softmax_j(K[:,i].Q[:,j]/16)
__global__ __launch_bounds__(256, 2) void k_demo_fused() {
    const int t = threadIdx.x;
    const int itile = blockIdx.x;        // 0..48
    const int bh = blockIdx.y;           // 0..31
    const int b = bh >> 3, h = bh & 7;
    const float* Kp = g_dk + ((long)b * 256 + h * 32) * DEMO_TOK;
    const float* Qp = g_dq + ((long)b * 256 + h * 32) * DEMO_TOK;
    const float* Vp = g_dv + ((long)b * 256 + h * 32) * DEMO_TOK;
    __shared__ float Ks[512];            // [c(32)][i(16)]
    __shared__ float Big[7488];          // phase1: Qs[8][16][52]; phase3: Vt[16][13][36]
    const int r = t >> 4, g = t & 15;
    float acc[49];
#pragma unroll
    for (int jj = 0; jj < 49; jj++) acc[jj] = 0.f;

    for (int e = t; e < 512; e += 256) {
        int c = e >> 4, ii = e & 15;
        Ks[c * 16 + ii] = Kp[(long)c * DEMO_TOK + itile * 16 + ii];
    }
    // ---- phase 1: scores ----
    for (int cb = 0; cb < 4; cb++) {
        __syncthreads();
        for (int e = t; e < 8 * 784; e += 256) {
            int c = e / 784, j = e - c * 784;
            Big[c * 832 + (j / 49) * 52 + (j % 49)] = Qp[(long)(cb * 8 + c) * DEMO_TOK + j];
        }
        __syncthreads();
#pragma unroll
        for (int cc = 0; cc < 8; cc++) {
            float a = Ks[(cb * 8 + cc) * 16 + r];
            const float* q = &Big[cc * 832 + g * 52];
#pragma unroll
            for (int v = 0; v < 12; v++) {
                float4 qq = *(const float4*)(q + v * 4);
                acc[v*4+0] += a * qq.x; acc[v*4+1] += a * qq.y;
                acc[v*4+2] += a * qq.z; acc[v*4+3] += a * qq.w;
            }
            acc[48] += a * q[48];
        }
    }
    // ---- phase 2: softmax over j (16 g-lanes per row) ----
    float mx = -1e30f;
#pragma unroll
    for (int jj = 0; jj < 49; jj++) { acc[jj] *= INV_TEMP; mx = fmaxf(mx, acc[jj]); }
#pragma unroll
    for (int o = 8; o; o >>= 1) mx = fmaxf(mx, __shfl_xor_sync(0xffffffffu, mx, o));
    float sm = 0.f;
#pragma unroll
    for (int jj = 0; jj < 49; jj++) { float p = __expf(acc[jj] - mx); acc[jj] = p; sm += p; }
#pragma unroll
    for (int o = 8; o; o >>= 1) sm += __shfl_xor_sync(0xffffffffu, sm, o);
    float inv = 1.f / sm;
#pragma unroll
    for (int jj = 0; jj < 49; jj++) acc[jj] *= inv;   // p now in registers

    // ---- phase 3: AV with register p, transposed V tiles ----
    float pacc[32];
#pragma unroll
    for (int c = 0; c < 32; c++) pacc[c] = 0.f;
#pragma unroll
    for (int tile = 0; tile < 4; tile++) {
        const int jj0 = tile * 13;
        const int njj = (tile < 3) ? 13 : 10;
        __syncthreads();
        for (int e = t; e < 512 * njj; e += 256) {
            int dj = e % njj;
            int gg = (e / njj) & 15;
            int c  = e / (njj * 16);
            Big[(gg * 13 + dj) * 36 + c] = Vp[(long)c * DEMO_TOK + gg * 49 + jj0 + dj];
        }
        __syncthreads();
#pragma unroll
        for (int dj = 0; dj < 13; dj++) {
            if (jj0 + dj >= 49) break;          // compile-time resolved (tile unrolled)
            float pr = acc[jj0 + dj];
            const float* vb = &Big[(g * 13 + dj) * 36];
#pragma unroll
            for (int cq = 0; cq < 8; cq++) {
                float4 v = *(const float4*)&vb[cq * 4];
                pacc[cq*4+0] += v.x * pr; pacc[cq*4+1] += v.y * pr;
                pacc[cq*4+2] += v.z * pr; pacc[cq*4+3] += v.w * pr;
            }
        }
    }
    // reduce over the 16 g-lanes (low 4 bits of lane id)
#pragma unroll
    for (int c = 0; c < 32; c++) {
        float v = pacc[c];
        v += __shfl_xor_sync(0xffffffffu, v, 1);
        v += __shfl_xor_sync(0xffffffffu, v, 2);
        v += __shfl_xor_sync(0xffffffffu, v, 4);
        v += __shfl_xor_sync(0xffffffffu, v, 8);
        pacc[c] = v;
    }
    if (g == 0) {
        float* op = g_dvatt + ((long)b * 256 + h * 32) * DEMO_TOK + itile * 16 + r;
#pragma unroll
        for (int c = 0; c < 32; c++) op[(long)c * DEMO_TOK] = pacc[c];
    }
}

// ---------------- fused obs attention: scores + softmax + AV (k-split) ----------------
// block: (z in 384) x (khalf in 2); each handles 490 keys in 8 tiles of 64.
// out[c,j] = sum_k catv[c,k] * softmax_j(catk[:,k].Q[:,j]/16)[j]
__global__ __launch_bounds__(256, 2) void k_obs_fused(float* __restrict__ part) {
    extern __shared__ float smem[];
    float* Ps = smem;              // [64][200]
    float* Qs = smem + 12800;      // [32][4][52]
    float* KV = smem + 19456;      // Ks[32][64] (phase A) / Vt[64][36] (phase B)
    const int z = blockIdx.x;                  // b*96 + tt*8 + h
    const int khalf = blockIdx.y;
    const int b = z / 96, tt = (z >> 3) % 12, h = z & 7;
    const int t = threadIdx.x;
    const float* Kd = g_dk    + ((long)b * 256 + h * 32) * DEMO_TOK;
    const float* Ko = g_ok    + ((long)b * 256 + h * 32) * OBS_TOK + tt * 196;
    const float* Vd = g_dvatt + ((long)b * 256 + h * 32) * DEMO_TOK;
    const float* Vo = g_ov    + ((long)b * 256 + h * 32) * OBS_TOK + tt * 196;
    const float* Qp = g_oq    + ((long)b * 256 + h * 32) * OBS_TOK + tt * 196;

    // Q resident for the whole block
    for (int e = t; e < 6272; e += 256) {
        int c = e / 196, j = e - c * 196;
        Qs[c * 208 + (j / 49) * 52 + (j % 49)] = Qp[(long)c * OBS_TOK + j];
    }
    const int r = t >> 2, gq = t & 3;          // phase A layout
    const int w = t >> 5, jg = t & 31;         // phase B layout (warp = 4 channels)
    const bool has7 = (jg < 4);
    const int kbase = khalf * 490;
    float out[4][7];
#pragma unroll
    for (int cc = 0; cc < 4; cc++)
#pragma unroll
        for (int q = 0; q < 7; q++) out[cc][q] = 0.f;

    for (int kt = 0; kt < 8; kt++) {
        const int k0 = kbase + kt * 64;
        __syncthreads();
        // K tile
        for (int e = t; e < 2048; e += 256) {
            int c = e >> 6, ii = e & 63;
            int kl = kt * 64 + ii, kg = k0 + ii;
            float v = 0.f;
            if (kl < 490)
                v = (kg < DEMO_TOK) ? Kd[(long)c * DEMO_TOK + kg]
                                    : Ko[(long)c * OBS_TOK + (kg - DEMO_TOK)];
            KV[c * 64 + ii] = v;
        }
        __syncthreads();
        // scores for 64 rows x 196 j
        float acc[49];
#pragma unroll
        for (int jj = 0; jj < 49; jj++) acc[jj] = 0.f;
#pragma unroll
        for (int c = 0; c < 32; c++) {
            float a = KV[c * 64 + r];
            const float* q = &Qs[c * 208 + gq * 52];
#pragma unroll
            for (int v = 0; v < 12; v++) {
                float4 qq = *(const float4*)(q + v * 4);
                acc[v*4+0] += a * qq.x; acc[v*4+1] += a * qq.y;
                acc[v*4+2] += a * qq.z; acc[v*4+3] += a * qq.w;
            }
            acc[48] += a * q[48];
        }
        // softmax over j (4 lanes per row)
        float mx = -1e30f;
#pragma unroll
        for (int jj = 0; jj < 49; jj++) { acc[jj] *= INV_TEMP; mx = fmaxf(mx, acc[jj]); }
        mx = fmaxf(mx, __shfl_xor_sync(0xffffffffu, mx, 1));
        mx = fmaxf(mx, __shfl_xor_sync(0xffffffffu, mx, 2));
        float sm = 0.f;
#pragma unroll
        for (int jj = 0; jj < 49; jj++) { float p = __expf(acc[jj] - mx); acc[jj] = p; sm += p; }
        sm += __shfl_xor_sync(0xffffffffu, sm, 1);
        sm += __shfl_xor_sync(0xffffffffu, sm, 2);
        float inv = 1.f / sm;
        {
            float* pr = &Ps[r * 200 + gq * 49];
#pragma unroll
            for (int jj = 0; jj < 49; jj++) pr[jj] = acc[jj] * inv;
        }
        __syncthreads();
        // V tile transposed: Vt[k][c]
        for (int e = t; e < 2048; e += 256) {
            int c = e >> 6, ii = e & 63;
            int kl = kt * 64 + ii, kg = k0 + ii;
            float v = 0.f;
            if (kl < 490)
                v = (kg < DEMO_TOK) ? Vd[(long)c * DEMO_TOK + kg]
                                    : Vo[(long)c * OBS_TOK + (kg - DEMO_TOK)];
            KV[ii * 36 + c] = v;
        }
        __syncthreads();
        // AV accumulation: warp w owns channels 4w..4w+3, lane jg owns j = jg+32q
#pragma unroll 4
        for (int k = 0; k < 64; k++) {
            float4 v4 = *(const float4*)&KV[k * 36 + w * 4];
            const float* pr = &Ps[k * 200 + jg];
            float p0 = pr[0],  p1 = pr[32], p2 = pr[64];
            float p3 = pr[96], p4 = pr[128], p5 = pr[160];
            float p6 = has7 ? pr[192] : 0.f;
            out[0][0] += v4.x*p0; out[1][0] += v4.y*p0; out[2][0] += v4.z*p0; out[3][0] += v4.w*p0;
            out[0][1] += v4.x*p1; out[1][1] += v4.y*p1; out[2][1] += v4.z*p1; out[3][1] += v4.w*p1;
            out[0][2] += v4.x*p2; out[1][2] += v4.y*p2; out[2][2] += v4.z*p2; out[3][2] += v4.w*p2;
            out[0][3] += v4.x*p3; out[1][3] += v4.y*p3; out[2][3] += v4.z*p3; out[3][3] += v4.w*p3;
            out[0][4] += v4.x*p4; out[1][4] += v4.y*p4; out[2][4] += v4.z*p4; out[3][4] += v4.w*p4;
            out[0][5] += v4.x*p5; out[1][5] += v4.y*p5; out[2][5] += v4.z*p5; out[3][5] += v4.w*p5;
            out[0][6] += v4.x*p6; out[1][6] += v4.y*p6; out[2][6] += v4.z*p6; out[3][6] += v4.w*p6;
        }
    }
    float* op = part + ((long)(khalf * 384 + z)) * 6272;
#pragma unroll
    for (int cc = 0; cc < 4; cc++)
#pragma unroll
        for (int q = 0; q < 7; q++) {
            int j = jg + 32 * q;
            if (j < 196) op[(w * 4 + cc) * 196 + j] = out[cc][q];
        }
}

// ---------------- merge obs AV partials into g_mg (conv layout) ----------------
__global__ void k_merge(const float* __restrict__ part) {
    int z = blockIdx.y;
    int e = blockIdx.x * 256 + threadIdx.x;
    if (e >= 6272) return;
    int c = e / 196, j = e - c * 196;
    int b = z / 96, tt = (z >> 3) % 12, h = z & 7;
    float v = part[(long)z * 6272 + e] + part[(long)(384 + z) * 6272 + e];
    g_mg[((long)b * 256 + h * 32 + c) * OBS_TOK + tt * 196 + j] = v;
}

// ---------------- BatchNorm stats ----------------
__global__ void k_bnstats() {
    const int c = blockIdx.x;
    float s = 0.f, s2 = 0.f;
    for (int e = threadIdx.x; e < BB * THW; e += 256) {
        int b = e / THW, k = e - b * THW;
        float v = g_x[(long)b * CTHW + (long)c * THW + k];
        s += v; s2 += v * v;
    }
#pragma unroll
    for (int o = 16; o; o >>= 1) {
        s  += __shfl_xor_sync(0xffffffffu, s, o);
        s2 += __shfl_xor_sync(0xffffffffu, s2, o);
    }
    __shared__ float ws[8], ws2[8];
    int w = threadIdx.x >> 5;
    if ((threadIdx.x & 31) == 0) { ws[w] = s; ws2[w] = s2; }
    __syncthreads();
    if (threadIdx.x == 0) {
        float S = 0.f, S2 = 0.f;
#pragma unroll
        for (int i = 0; i < 8; i++) { S += ws[i]; S2 += ws2[i]; }
        float m = S * (1.f / 12544.f);
        float var = S2 * (1.f / 12544.f) - m * m;
        g_mean[c] = m;
        g_istd[c] = rsqrtf(var + EPSV);
    }
}

// ---------------- BatchNorm apply ----------------
__global__ void k_bnapply(const float* __restrict__ gamma, const float* __restrict__ beta,
                          float* __restrict__ out) {
    int e = blockIdx.x * 256 + threadIdx.x;   // 802816 float4 over full tensor
    int c = (e / 784) & 255;
    float4 v = ((const float4*)g_x)[e];
    float a = gamma[c] * g_istd[c];
    float b2 = beta[c] - g_mean[c] * a;
    v.x = v.x * a + b2; v.y = v.y * a + b2; v.z = v.z * a + b2; v.w = v.w * a + b2;
    ((float4*)out)[e] = v;
}

// ---------------- host orchestration ----------------
extern "C" void kernel_launch(void* const* d_in, const int* in_sizes, int n_in,
                              void* d_out, int out_size) {
    const float* x    = (const float*)d_in[0];
    const float* w_dq = (const float*)d_in[1];
    const float* w_dk = (const float*)d_in[2];
    const float* w_dv = (const float*)d_in[3];
    const float* w_oq = (const float*)d_in[4];
    const float* w_ok = (const float*)d_in[5];
    const float* w_ov = (const float*)d_in[6];
    const float* w_oo = (const float*)d_in[7];
    const float* gam  = (const float*)d_in[8];
    const float* bet  = (const float*)d_in[9];
    float* out = (float*)d_out;

    float *p_x, *p_dq, *p_dk, *p_dv, *p_oq, *p_ok, *p_ov, *p_mg, *p_part;
    cudaGetSymbolAddress((void**)&p_x,  g_x);
    cudaGetSymbolAddress((void**)&p_dq, g_dq);
    cudaGetSymbolAddress((void**)&p_dk, g_dk);
    cudaGetSymbolAddress((void**)&p_dv, g_dv);
    cudaGetSymbolAddress((void**)&p_oq, g_oq);
    cudaGetSymbolAddress((void**)&p_ok, g_ok);
    cudaGetSymbolAddress((void**)&p_ov, g_ov);
    cudaGetSymbolAddress((void**)&p_mg, g_mg);
    cudaGetSymbolAddress((void**)&p_part, g_part);

    cudaFuncSetAttribute(k_obs_fused, cudaFuncAttributeMaxDynamicSharedMemorySize, 87040);

    // FIX (round-2 bug): full tensor = 802816 float4 -> 3136 blocks, not 784.
    k_copy<<<3136, 256>>>((const float4*)x);

    const long xbs = (long)CTHW;
    const long dbs = (long)256 * DEMO_TOK;
    const long obs = (long)256 * OBS_TOK;
    dim3 cg_demo(13, 12, BB), cg_obs(37, 12, BB), cg_out(37, 4, BB);

    for (int l = 0; l < 3; l++) {
        const int WO = l * 256 * 256;
        // fused QKV convs
        k_conv3<<<cg_demo, 256>>>(w_dq + WO, w_dk + WO, w_dv + WO,
                                  p_x, THW, 0, xbs,
                                  p_dq, p_dk, p_dv, DEMO_TOK, 0, dbs, DEMO_TOK, 0);
        k_conv3<<<cg_obs, 256>>>(w_oq + WO, w_ok + WO, w_ov + WO,
                                 p_x, THW, DEMO_TOK, xbs,
                                 p_oq, p_ok, p_ov, OBS_TOK, 0, obs, OBS_TOK, 0);
        // fused attentions
        k_demo_fused<<<dim3(49, 32), 256>>>();
        k_obs_fused<<<dim3(384, 2), 256, 87040>>>(p_part);
        k_merge<<<dim3(25, 384), 256>>>(p_part);
        // output conv + relu + residual (in place into g_x obs region)
        k_conv3<<<cg_out, 256>>>(w_oo + WO, w_oo + WO, w_oo + WO,
                                 p_mg, OBS_TOK, 0, obs,
                                 p_x, p_x, p_x, THW, DEMO_TOK, xbs, OBS_TOK, 1);
        // batchnorm
        k_bnstats<<<256, 256>>>();
        k_bnapply<<<3136, 256>>>(gam + l * 256, bet + l * 256, (l == 2) ? out : p_x);
    }
}

// round 5
// speedup vs baseline: 1.6836x; 1.0760x over previous
#include <cuda_runtime.h>

// ---------------- problem constants ----------------
#define BB 4
#define THW 3136          // 16*14*14
#define DEMO_TOK 784
#define OBS_TOK 2352
#define INV_TEMP 0.0625f  // 1/sqrt(256)
#define EPSV 1e-5f
#define CTHW (256*THW)    // 802816

// ---------------- scratch (device globals; allocation-free) ----------------
__device__ __align__(256) float g_x[BB*CTHW];
__device__ __align__(256) float g_dq[BB*256*DEMO_TOK];
__device__ __align__(256) float g_dk[BB*256*DEMO_TOK];
__device__ __align__(256) float g_dv[BB*256*DEMO_TOK];
__device__ __align__(256) float g_dvatt[BB*256*DEMO_TOK];
__device__ __align__(256) float g_oq[BB*256*OBS_TOK];
__device__ __align__(256) float g_ok[BB*256*OBS_TOK];
__device__ __align__(256) float g_ov[BB*256*OBS_TOK];
__device__ __align__(256) float g_mg[BB*256*OBS_TOK];
__device__ __align__(256) float g_part[2*384*32*196];   // obs AV partials (k-split)
__device__ float g_mean[256];
__device__ float g_istd[256];

// ---------------- copy input -> g_x ----------------
// total = BB*CTHW = 3,211,264 floats = 802,816 float4 -> 3136 blocks x 256 thr
__global__ void k_copy(const float4* __restrict__ src) {
    int e = blockIdx.x * 256 + threadIdx.x;
    ((float4*)g_x)[e] = src[e];
}

// ---------------- fused triple 1x1-conv GEMM ----------------
__global__ __launch_bounds__(256) void k_conv3(
    const float* __restrict__ W0, const float* __restrict__ W1, const float* __restrict__ W2,
    const float* __restrict__ X, int ldx, int xoff, long xbstr,
    float* __restrict__ O0, float* __restrict__ O1, float* __restrict__ O2,
    int ldo, int ooff, long obstr, int N, int fuse)
{
    __shared__ float As[32][68];
    __shared__ float Bs[32][68];
    const int t  = threadIdx.x;
    const int b  = blockIdx.z;
    const int my = blockIdx.y;
    const int sel = my >> 2;
    const int m0  = (my & 3) * 64;
    const int n0  = blockIdx.x * 64;
    const float* W = (sel == 0) ? W0 : ((sel == 1) ? W1 : W2);
    float* Obase   = (sel == 0) ? O0 : ((sel == 1) ? O1 : O2);
    const float* Xb = X + b * xbstr + xoff;
    const int ty = t >> 4, tx = t & 15;
    float acc[4][4];
#pragma unroll
    for (int i = 0; i < 4; i++)
#pragma unroll
        for (int j = 0; j < 4; j++) acc[i][j] = 0.f;

    for (int k0 = 0; k0 < 256; k0 += 32) {
#pragma unroll
        for (int e = t; e < 512; e += 256) {
            int m = e >> 3, k4 = e & 7;
            float4 w4 = *(const float4*)&W[(m0 + m) * 256 + k0 + k4 * 4];
            As[k4*4+0][m] = w4.x; As[k4*4+1][m] = w4.y;
            As[k4*4+2][m] = w4.z; As[k4*4+3][m] = w4.w;
        }
#pragma unroll
        for (int e = t; e < 512; e += 256) {
            int k = e >> 4, n4 = e & 15;
            float4 x4 = make_float4(0.f, 0.f, 0.f, 0.f);
            if (n0 + n4 * 4 < N)
                x4 = *(const float4*)&Xb[(long)(k0 + k) * ldx + n0 + n4 * 4];
            *(float4*)&Bs[k][n4 * 4] = x4;
        }
        __syncthreads();
#pragma unroll
        for (int k = 0; k < 32; k++) {
            float4 ra = *(const float4*)&As[k][ty * 4];
            float4 rb = *(const float4*)&Bs[k][tx * 4];
            float a[4] = {ra.x, ra.y, ra.z, ra.w};
            float bv[4] = {rb.x, rb.y, rb.z, rb.w};
#pragma unroll
            for (int i = 0; i < 4; i++)
#pragma unroll
                for (int j = 0; j < 4; j++) acc[i][j] += a[i] * bv[j];
        }
        __syncthreads();
    }
    float* Ob = Obase + b * obstr + ooff;
#pragma unroll
    for (int i = 0; i < 4; i++) {
        int m = m0 + ty * 4 + i;
#pragma unroll
        for (int j = 0; j < 4; j++) {
            int n = n0 + tx * 4 + j;
            if (n < N) {
                float* p = Ob + (long)m * ldo + n;
                if (fuse) *p = *p + fmaxf(acc[i][j], 0.f);
                else      *p = acc[i][j];
            }
        }
    }
}

// ---------------- fused demo attention: scores + softmax + AV ----------------
// LAYOUT SWAP vs round 3: r = t&15 (row), g = t>>4 (j-group of 49).
// Each warp spans only 2 g values -> Q/V float4 LDS are 2-distinct (broadcast),
// cutting smem crossbar traffic ~4x. Softmax & output reductions over g now
// cross warps -> small smem reductions via Red[16g][16r].
__global__ __launch_bounds__(256, 2) void k_demo_fused() {
    const int t = threadIdx.x;
    const int itile = blockIdx.x;        // 0..48
    const int bh = blockIdx.y;           // 0..31
    const int b = bh >> 3, h = bh & 7;
    const float* Kp = g_dk + ((long)b * 256 + h * 32) * DEMO_TOK;
    const float* Qp = g_dq + ((long)b * 256 + h * 32) * DEMO_TOK;
    const float* Vp = g_dv + ((long)b * 256 + h * 32) * DEMO_TOK;
    __shared__ float Ks[512];            // [c(32)][i(16)]
    __shared__ float Red[256];           // [g(16)][r(16)] reduction staging
    __shared__ float Big[7488];          // phase1: Qs[8][16][52]; phase3: Vt / pacc staging
    const int r = t & 15;                // row within tile (SWAPPED)
    const int g = t >> 4;                // j-group        (SWAPPED)
    float acc[49];
#pragma unroll
    for (int jj = 0; jj < 49; jj++) acc[jj] = 0.f;

    for (int e = t; e < 512; e += 256) {
        int c = e >> 4, ii = e & 15;
        Ks[c * 16 + ii] = Kp[(long)c * DEMO_TOK + itile * 16 + ii];
    }
    // ---- phase 1: scores ----
    for (int cb = 0; cb < 4; cb++) {
        __syncthreads();
        for (int e = t; e < 8 * 784; e += 256) {
            int c = e / 784, j = e - c * 784;
            Big[c * 832 + (j / 49) * 52 + (j % 49)] = Qp[(long)(cb * 8 + c) * DEMO_TOK + j];
        }
        __syncthreads();
#pragma unroll
        for (int cc = 0; cc < 8; cc++) {
            float a = Ks[(cb * 8 + cc) * 16 + r];
            const float* q = &Big[cc * 832 + g * 52];
#pragma unroll
            for (int v = 0; v < 12; v++) {
                float4 qq = *(const float4*)(q + v * 4);
                acc[v*4+0] += a * qq.x; acc[v*4+1] += a * qq.y;
                acc[v*4+2] += a * qq.z; acc[v*4+3] += a * qq.w;
            }
            acc[48] += a * q[48];
        }
    }
    // ---- phase 2: softmax over j; reduce over 16 g via smem ----
    float mx = -1e30f;
#pragma unroll
    for (int jj = 0; jj < 49; jj++) { acc[jj] *= INV_TEMP; mx = fmaxf(mx, acc[jj]); }
    __syncthreads();                     // Big (Qs) no longer needed; Red fresh
    Red[g * 16 + r] = mx;
    __syncthreads();
    float gm = Red[r];
#pragma unroll
    for (int gg = 1; gg < 16; gg++) gm = fmaxf(gm, Red[gg * 16 + r]);
    __syncthreads();
    float sm = 0.f;
#pragma unroll
    for (int jj = 0; jj < 49; jj++) { float p = __expf(acc[jj] - gm); acc[jj] = p; sm += p; }
    Red[g * 16 + r] = sm;
    __syncthreads();
    float gs = Red[r];
#pragma unroll
    for (int gg = 1; gg < 16; gg++) gs += Red[gg * 16 + r];
    float inv = 1.f / gs;
#pragma unroll
    for (int jj = 0; jj < 49; jj++) acc[jj] *= inv;   // p in registers

    // ---- phase 3: AV. V tiles transposed in smem; reads broadcast per warp ----
    float pacc[32];
#pragma unroll
    for (int c = 0; c < 32; c++) pacc[c] = 0.f;
#pragma unroll
    for (int tile = 0; tile < 4; tile++) {
        __syncthreads();
        // load Vt: Big[(gg*13+dj)*36 + c] = V[c, gg*49 + tile*13 + dj]
        for (int e = t; e < 6656; e += 256) {      // 32c * 16g * 13dj
            int dj = e % 13;
            int rest = e / 13;                     // 0..511
            int gg = rest & 15, c = rest >> 4;
            int jl = tile * 13 + dj;
            float v = (jl < 49) ? Vp[(long)c * DEMO_TOK + gg * 49 + jl] : 0.f;
            Big[(gg * 13 + dj) * 36 + c] = v;
        }
        __syncthreads();
#pragma unroll
        for (int dj = 0; dj < 13; dj++) {
            const int jj = tile * 13 + dj;
            if (jj >= 49) break;                   // compile-time (tile,dj unrolled)
            float pr = acc[jj];
            const float* vb = &Big[(g * 13 + dj) * 36];
#pragma unroll
            for (int cq = 0; cq < 8; cq++) {
                float4 v = *(const float4*)&vb[cq * 4];
                pacc[cq*4+0] += v.x * pr; pacc[cq*4+1] += v.y * pr;
                pacc[cq*4+2] += v.z * pr; pacc[cq*4+3] += v.w * pr;
            }
        }
    }
    // ---- reduce pacc over 16 g via smem, 2 chunks of 16 channels ----
#pragma unroll
    for (int ch = 0; ch < 2; ch++) {
        __syncthreads();
#pragma unroll
        for (int cc = 0; cc < 16; cc++)
            Big[t * 17 + cc] = pacc[ch * 16 + cc];   // stride 17: conflict-free scalar
        __syncthreads();
        int rr = t >> 4, cc = t & 15;
        float s = 0.f;
#pragma unroll
        for (int gg = 0; gg < 16; gg++)
            s += Big[(gg * 16 + rr) * 17 + cc];
        g_dvatt[((long)b * 256 + h * 32 + ch * 16 + cc) * DEMO_TOK + itile * 16 + rr] = s;
    }
}

// ---------------- fused obs attention: scores + softmax + AV (k-split) ----------------
// unchanged from round 3 (passing)
__global__ __launch_bounds__(256, 2) void k_obs_fused(float* __restrict__ part) {
    extern __shared__ float smem[];
    float* Ps = smem;              // [64][200]
    float* Qs = smem + 12800;      // [32][4][52]
    float* KV = smem + 19456;      // Ks[32][64] (phase A) / Vt[64][36] (phase B)
    const int z = blockIdx.x;                  // b*96 + tt*8 + h
    const int khalf = blockIdx.y;
    const int b = z / 96, tt = (z >> 3) % 12, h = z & 7;
    const int t = threadIdx.x;
    const float* Kd = g_dk    + ((long)b * 256 + h * 32) * DEMO_TOK;
    const float* Ko = g_ok    + ((long)b * 256 + h * 32) * OBS_TOK + tt * 196;
    const float* Vd = g_dvatt + ((long)b * 256 + h * 32) * DEMO_TOK;
    const float* Vo = g_ov    + ((long)b * 256 + h * 32) * OBS_TOK + tt * 196;
    const float* Qp = g_oq    + ((long)b * 256 + h * 32) * OBS_TOK + tt * 196;

    for (int e = t; e < 6272; e += 256) {
        int c = e / 196, j = e - c * 196;
        Qs[c * 208 + (j / 49) * 52 + (j % 49)] = Qp[(long)c * OBS_TOK + j];
    }
    const int r = t >> 2, gq = t & 3;
    const int w = t >> 5, jg = t & 31;
    const bool has7 = (jg < 4);
    const int kbase = khalf * 490;
    float out[4][7];
#pragma unroll
    for (int cc = 0; cc < 4; cc++)
#pragma unroll
        for (int q = 0; q < 7; q++) out[cc][q] = 0.f;

    for (int kt = 0; kt < 8; kt++) {
        const int k0 = kbase + kt * 64;
        __syncthreads();
        for (int e = t; e < 2048; e += 256) {
            int c = e >> 6, ii = e & 63;
            int kl = kt * 64 + ii, kg = k0 + ii;
            float v = 0.f;
            if (kl < 490)
                v = (kg < DEMO_TOK) ? Kd[(long)c * DEMO_TOK + kg]
                                    : Ko[(long)c * OBS_TOK + (kg - DEMO_TOK)];
            KV[c * 64 + ii] = v;
        }
        __syncthreads();
        float acc[49];
#pragma unroll
        for (int jj = 0; jj < 49; jj++) acc[jj] = 0.f;
#pragma unroll
        for (int c = 0; c < 32; c++) {
            float a = KV[c * 64 + r];
            const float* q = &Qs[c * 208 + gq * 52];
#pragma unroll
            for (int v = 0; v < 12; v++) {
                float4 qq = *(const float4*)(q + v * 4);
                acc[v*4+0] += a * qq.x; acc[v*4+1] += a * qq.y;
                acc[v*4+2] += a * qq.z; acc[v*4+3] += a * qq.w;
            }
            acc[48] += a * q[48];
        }
        float mx = -1e30f;
#pragma unroll
        for (int jj = 0; jj < 49; jj++) { acc[jj] *= INV_TEMP; mx = fmaxf(mx, acc[jj]); }
        mx = fmaxf(mx, __shfl_xor_sync(0xffffffffu, mx, 1));
        mx = fmaxf(mx, __shfl_xor_sync(0xffffffffu, mx, 2));
        float sm = 0.f;
#pragma unroll
        for (int jj = 0; jj < 49; jj++) { float p = __expf(acc[jj] - mx); acc[jj] = p; sm += p; }
        sm += __shfl_xor_sync(0xffffffffu, sm, 1);
        sm += __shfl_xor_sync(0xffffffffu, sm, 2);
        float inv = 1.f / sm;
        {
            float* pr = &Ps[r * 200 + gq * 49];
#pragma unroll
            for (int jj = 0; jj < 49; jj++) pr[jj] = acc[jj] * inv;
        }
        __syncthreads();
        for (int e = t; e < 2048; e += 256) {
            int c = e >> 6, ii = e & 63;
            int kl = kt * 64 + ii, kg = k0 + ii;
            float v = 0.f;
            if (kl < 490)
                v = (kg < DEMO_TOK) ? Vd[(long)c * DEMO_TOK + kg]
                                    : Vo[(long)c * OBS_TOK + (kg - DEMO_TOK)];
            KV[ii * 36 + c] = v;
        }
        __syncthreads();
#pragma unroll 4
        for (int k = 0; k < 64; k++) {
            float4 v4 = *(const float4*)&KV[k * 36 + w * 4];
            const float* pr = &Ps[k * 200 + jg];
            float p0 = pr[0],  p1 = pr[32], p2 = pr[64];
            float p3 = pr[96], p4 = pr[128], p5 = pr[160];
            float p6 = has7 ? pr[192] : 0.f;
            out[0][0] += v4.x*p0; out[1][0] += v4.y*p0; out[2][0] += v4.z*p0; out[3][0] += v4.w*p0;
            out[0][1] += v4.x*p1; out[1][1] += v4.y*p1; out[2][1] += v4.z*p1; out[3][1] += v4.w*p1;
            out[0][2] += v4.x*p2; out[1][2] += v4.y*p2; out[2][2] += v4.z*p2; out[3][2] += v4.w*p2;
            out[0][3] += v4.x*p3; out[1][3] += v4.y*p3; out[2][3] += v4.z*p3; out[3][3] += v4.w*p3;
            out[0][4] += v4.x*p4; out[1][4] += v4.y*p4; out[2][4] += v4.z*p4; out[3][4] += v4.w*p4;
            out[0][5] += v4.x*p5; out[1][5] += v4.y*p5; out[2][5] += v4.z*p5; out[3][5] += v4.w*p5;
            out[0][6] += v4.x*p6; out[1][6] += v4.y*p6; out[2][6] += v4.z*p6; out[3][6] += v4.w*p6;
        }
    }
    float* op = part + ((long)(khalf * 384 + z)) * 6272;
#pragma unroll
    for (int cc = 0; cc < 4; cc++)
#pragma unroll
        for (int q = 0; q < 7; q++) {
            int j = jg + 32 * q;
            if (j < 196) op[(w * 4 + cc) * 196 + j] = out[cc][q];
        }
}

// ---------------- merge obs AV partials into g_mg (conv layout) ----------------
__global__ void k_merge(const float* __restrict__ part) {
    int z = blockIdx.y;
    int e = blockIdx.x * 256 + threadIdx.x;
    if (e >= 6272) return;
    int c = e / 196, j = e - c * 196;
    int b = z / 96, tt = (z >> 3) % 12, h = z & 7;
    float v = part[(long)z * 6272 + e] + part[(long)(384 + z) * 6272 + e];
    g_mg[((long)b * 256 + h * 32 + c) * OBS_TOK + tt * 196 + j] = v;
}

// ---------------- BatchNorm stats ----------------
__global__ void k_bnstats() {
    const int c = blockIdx.x;
    float s = 0.f, s2 = 0.f;
    for (int e = threadIdx.x; e < BB * THW; e += 256) {
        int b = e / THW, k = e - b * THW;
        float v = g_x[(long)b * CTHW + (long)c * THW + k];
        s += v; s2 += v * v;
    }
#pragma unroll
    for (int o = 16; o; o >>= 1) {
        s  += __shfl_xor_sync(0xffffffffu, s, o);
        s2 += __shfl_xor_sync(0xffffffffu, s2, o);
    }
    __shared__ float ws[8], ws2[8];
    int w = threadIdx.x >> 5;
    if ((threadIdx.x & 31) == 0) { ws[w] = s; ws2[w] = s2; }
    __syncthreads();
    if (threadIdx.x == 0) {
        float S = 0.f, S2 = 0.f;
#pragma unroll
        for (int i = 0; i < 8; i++) { S += ws[i]; S2 += ws2[i]; }
        float m = S * (1.f / 12544.f);
        float var = S2 * (1.f / 12544.f) - m * m;
        g_mean[c] = m;
        g_istd[c] = rsqrtf(var + EPSV);
    }
}

// ---------------- BatchNorm apply ----------------
__global__ void k_bnapply(const float* __restrict__ gamma, const float* __restrict__ beta,
                          float* __restrict__ out) {
    int e = blockIdx.x * 256 + threadIdx.x;   // 802816 float4 over full tensor
    int c = (e / 784) & 255;
    float4 v = ((const float4*)g_x)[e];
    float a = gamma[c] * g_istd[c];
    float b2 = beta[c] - g_mean[c] * a;
    v.x = v.x * a + b2; v.y = v.y * a + b2; v.z = v.z * a + b2; v.w = v.w * a + b2;
    ((float4*)out)[e] = v;
}

// ---------------- host orchestration ----------------
extern "C" void kernel_launch(void* const* d_in, const int* in_sizes, int n_in,
                              void* d_out, int out_size) {
    const float* x    = (const float*)d_in[0];
    const float* w_dq = (const float*)d_in[1];
    const float* w_dk = (const float*)d_in[2];
    const float* w_dv = (const float*)d_in[3];
    const float* w_oq = (const float*)d_in[4];
    const float* w_ok = (const float*)d_in[5];
    const float* w_ov = (const float*)d_in[6];
    const float* w_oo = (const float*)d_in[7];
    const float* gam  = (const float*)d_in[8];
    const float* bet  = (const float*)d_in[9];
    float* out = (float*)d_out;

    float *p_x, *p_dq, *p_dk, *p_dv, *p_oq, *p_ok, *p_ov, *p_mg, *p_part;
    cudaGetSymbolAddress((void**)&p_x,  g_x);
    cudaGetSymbolAddress((void**)&p_dq, g_dq);
    cudaGetSymbolAddress((void**)&p_dk, g_dk);
    cudaGetSymbolAddress((void**)&p_dv, g_dv);
    cudaGetSymbolAddress((void**)&p_oq, g_oq);
    cudaGetSymbolAddress((void**)&p_ok, g_ok);
    cudaGetSymbolAddress((void**)&p_ov, g_ov);
    cudaGetSymbolAddress((void**)&p_mg, g_mg);
    cudaGetSymbolAddress((void**)&p_part, g_part);

    cudaFuncSetAttribute(k_obs_fused, cudaFuncAttributeMaxDynamicSharedMemorySize, 87040);

    k_copy<<<3136, 256>>>((const float4*)x);

    const long xbs = (long)CTHW;
    const long dbs = (long)256 * DEMO_TOK;
    const long obs = (long)256 * OBS_TOK;
    dim3 cg_demo(13, 12, BB), cg_obs(37, 12, BB), cg_out(37, 4, BB);

    for (int l = 0; l < 3; l++) {
        const int WO = l * 256 * 256;
        k_conv3<<<cg_demo, 256>>>(w_dq + WO, w_dk + WO, w_dv + WO,
                                  p_x, THW, 0, xbs,
                                  p_dq, p_dk, p_dv, DEMO_TOK, 0, dbs, DEMO_TOK, 0);
        k_conv3<<<cg_obs, 256>>>(w_oq + WO, w_ok + WO, w_ov + WO,
                                 p_x, THW, DEMO_TOK, xbs,
                                 p_oq, p_ok, p_ov, OBS_TOK, 0, obs, OBS_TOK, 0);
        k_demo_fused<<<dim3(49, 32), 256>>>();
        k_obs_fused<<<dim3(384, 2), 256, 87040>>>(p_part);
        k_merge<<<dim3(25, 384), 256>>>(p_part);
        k_conv3<<<cg_out, 256>>>(w_oo + WO, w_oo + WO, w_oo + WO,
                                 p_mg, OBS_TOK, 0, obs,
                                 p_x, p_x, p_x, THW, DEMO_TOK, xbs, OBS_TOK, 1);
        k_bnstats<<<256, 256>>>();
        k_bnapply<<<3136, 256>>>(gam + l * 256, bet + l * 256, (l == 2) ? out : p_x);
    }
}

// round 6
// speedup vs baseline: 1.7760x; 1.0549x over previous
#include <cuda_runtime.h>

// ---------------- problem constants ----------------
#define BB 4
#define THW 3136          // 16*14*14
#define DEMO_TOK 784
#define OBS_TOK 2352
#define INV_TEMP 0.0625f  // 1/sqrt(256)
#define EPSV 1e-5f
#define CTHW (256*THW)    // 802816

// ---------------- scratch (device globals; allocation-free) ----------------
__device__ __align__(256) float g_x[BB*CTHW];
__device__ __align__(256) float g_dq[BB*256*DEMO_TOK];
__device__ __align__(256) float g_dk[BB*256*DEMO_TOK];
__device__ __align__(256) float g_dv[BB*256*DEMO_TOK];
__device__ __align__(256) float g_dvatt[BB*256*DEMO_TOK];
__device__ __align__(256) float g_oq[BB*256*OBS_TOK];
__device__ __align__(256) float g_ok[BB*256*OBS_TOK];
__device__ __align__(256) float g_ov[BB*256*OBS_TOK];
__device__ __align__(256) float g_mg[BB*256*OBS_TOK];
__device__ __align__(256) float g_part[2*384*32*196];   // obs AV partials (k-split)
__device__ float g_mean[256];
__device__ float g_istd[256];

// ---------------- copy input -> g_x ----------------
// total = BB*CTHW = 3,211,264 floats = 802,816 float4 -> 3136 blocks x 256 thr
__global__ void k_copy(const float4* __restrict__ src) {
    int e = blockIdx.x * 256 + threadIdx.x;
    ((float4*)g_x)[e] = src[e];
}

// ---------------- fused triple 1x1-conv GEMM ----------------
__global__ __launch_bounds__(256) void k_conv3(
    const float* __restrict__ W0, const float* __restrict__ W1, const float* __restrict__ W2,
    const float* __restrict__ X, int ldx, int xoff, long xbstr,
    float* __restrict__ O0, float* __restrict__ O1, float* __restrict__ O2,
    int ldo, int ooff, long obstr, int N, int fuse)
{
    __shared__ float As[32][68];
    __shared__ float Bs[32][68];
    const int t  = threadIdx.x;
    const int b  = blockIdx.z;
    const int my = blockIdx.y;
    const int sel = my >> 2;
    const int m0  = (my & 3) * 64;
    const int n0  = blockIdx.x * 64;
    const float* W = (sel == 0) ? W0 : ((sel == 1) ? W1 : W2);
    float* Obase   = (sel == 0) ? O0 : ((sel == 1) ? O1 : O2);
    const float* Xb = X + b * xbstr + xoff;
    const int ty = t >> 4, tx = t & 15;
    float acc[4][4];
#pragma unroll
    for (int i = 0; i < 4; i++)
#pragma unroll
        for (int j = 0; j < 4; j++) acc[i][j] = 0.f;

    for (int k0 = 0; k0 < 256; k0 += 32) {
#pragma unroll
        for (int e = t; e < 512; e += 256) {
            int m = e >> 3, k4 = e & 7;
            float4 w4 = *(const float4*)&W[(m0 + m) * 256 + k0 + k4 * 4];
            As[k4*4+0][m] = w4.x; As[k4*4+1][m] = w4.y;
            As[k4*4+2][m] = w4.z; As[k4*4+3][m] = w4.w;
        }
#pragma unroll
        for (int e = t; e < 512; e += 256) {
            int k = e >> 4, n4 = e & 15;
            float4 x4 = make_float4(0.f, 0.f, 0.f, 0.f);
            if (n0 + n4 * 4 < N)
                x4 = *(const float4*)&Xb[(long)(k0 + k) * ldx + n0 + n4 * 4];
            *(float4*)&Bs[k][n4 * 4] = x4;
        }
        __syncthreads();
#pragma unroll
        for (int k = 0; k < 32; k++) {
            float4 ra = *(const float4*)&As[k][ty * 4];
            float4 rb = *(const float4*)&Bs[k][tx * 4];
            float a[4] = {ra.x, ra.y, ra.z, ra.w};
            float bv[4] = {rb.x, rb.y, rb.z, rb.w};
#pragma unroll
            for (int i = 0; i < 4; i++)
#pragma unroll
                for (int j = 0; j < 4; j++) acc[i][j] += a[i] * bv[j];
        }
        __syncthreads();
    }
    float* Ob = Obase + b * obstr + ooff;
#pragma unroll
    for (int i = 0; i < 4; i++) {
        int m = m0 + ty * 4 + i;
#pragma unroll
        for (int j = 0; j < 4; j++) {
            int n = n0 + tx * 4 + j;
            if (n < N) {
                float* p = Ob + (long)m * ldo + n;
                if (fuse) *p = *p + fmaxf(acc[i][j], 0.f);
                else      *p = acc[i][j];
            }
        }
    }
}

// ---------------- fused demo attention: scores + softmax + AV ----------------
// r = t&15 (row), g = t>>4 (j-group): warp spans 2 g values -> broadcast LDS.
// ROUND-6 CHANGE: loaders rewritten as constant-trip nested loops with
// thread-derived indices -- zero runtime div/mod (alu pipe was 48%).
__global__ __launch_bounds__(256, 2) void k_demo_fused() {
    const int t = threadIdx.x;
    const int itile = blockIdx.x;        // 0..48
    const int bh = blockIdx.y;           // 0..31
    const int b = bh >> 3, h = bh & 7;
    const float* Kp = g_dk + ((long)b * 256 + h * 32) * DEMO_TOK;
    const float* Qp = g_dq + ((long)b * 256 + h * 32) * DEMO_TOK;
    const float* Vp = g_dv + ((long)b * 256 + h * 32) * DEMO_TOK;
    __shared__ float Ks[512];            // [c(32)][i(16)]
    __shared__ float Red[256];           // [g(16)][r(16)] reduction staging
    __shared__ float Big[7488];          // phase1: Qs[8][16][52]; phase3: Vt / staging
    const int r = t & 15;                // row within tile
    const int g = t >> 4;                // j-group of 49
    const int wc = t >> 5;               // warp id = channel for phase-1 loader
    const int ln = t & 31;               // lane
    float acc[49];
#pragma unroll
    for (int jj = 0; jj < 49; jj++) acc[jj] = 0.f;

#pragma unroll
    for (int e = t; e < 512; e += 256) {
        int c = e >> 4, ii = e & 15;
        Ks[c * 16 + ii] = Kp[(long)c * DEMO_TOK + itile * 16 + ii];
    }
    // ---- phase 1: scores ----
    for (int cb = 0; cb < 4; cb++) {
        __syncthreads();
        // div-free Q loader: warp wc owns channel wc; jq x half constant loops
        {
            const float* qsrc = Qp + (long)(cb * 8 + wc) * DEMO_TOK;
            float* qdst = &Big[wc * 832];
#pragma unroll
            for (int jq = 0; jq < 16; jq++) {
#pragma unroll
                for (int half = 0; half < 2; half++) {
                    int jr = ln + half * 32;
                    if (jr < 49)
                        qdst[jq * 52 + jr] = qsrc[jq * 49 + jr];
                }
            }
        }
        __syncthreads();
#pragma unroll
        for (int cc = 0; cc < 8; cc++) {
            float a = Ks[(cb * 8 + cc) * 16 + r];
            const float* q = &Big[cc * 832 + g * 52];
#pragma unroll
            for (int v = 0; v < 12; v++) {
                float4 qq = *(const float4*)(q + v * 4);
                acc[v*4+0] += a * qq.x; acc[v*4+1] += a * qq.y;
                acc[v*4+2] += a * qq.z; acc[v*4+3] += a * qq.w;
            }
            acc[48] += a * q[48];
        }
    }
    // ---- phase 2: softmax over j; reduce over 16 g via smem ----
    float mx = -1e30f;
#pragma unroll
    for (int jj = 0; jj < 49; jj++) { acc[jj] *= INV_TEMP; mx = fmaxf(mx, acc[jj]); }
    __syncthreads();
    Red[g * 16 + r] = mx;
    __syncthreads();
    float gm = Red[r];
#pragma unroll
    for (int gg = 1; gg < 16; gg++) gm = fmaxf(gm, Red[gg * 16 + r]);
    __syncthreads();
    float sm = 0.f;
#pragma unroll
    for (int jj = 0; jj < 49; jj++) { float p = __expf(acc[jj] - gm); acc[jj] = p; sm += p; }
    Red[g * 16 + r] = sm;
    __syncthreads();
    float gs = Red[r];
#pragma unroll
    for (int gg = 1; gg < 16; gg++) gs += Red[gg * 16 + r];
    float inv = 1.f / gs;
#pragma unroll
    for (int jj = 0; jj < 49; jj++) acc[jj] *= inv;   // p in registers

    // ---- phase 3: AV. V tiles transposed in smem; div-free loader ----
    const int lgg = t >> 4;              // gg for loader
    const int lc0 = t & 15;              // low channel for loader
    float pacc[32];
#pragma unroll
    for (int c = 0; c < 32; c++) pacc[c] = 0.f;
#pragma unroll
    for (int tile = 0; tile < 4; tile++) {
        __syncthreads();
        // Big[(gg*13+dj)*36 + c] = V[c, gg*49 + tile*13 + dj], constant loops
#pragma unroll
        for (int ch = 0; ch < 2; ch++) {
            const float* vsrc = Vp + (long)(ch * 16 + lc0) * DEMO_TOK + lgg * 49 + tile * 13;
            float* vdst = &Big[lgg * 13 * 36 + ch * 16 + lc0];
#pragma unroll
            for (int dj = 0; dj < 13; dj++) {
                if (tile * 13 + dj < 49)              // compile-time per (tile,dj)
                    vdst[dj * 36] = vsrc[dj];
            }
        }
        __syncthreads();
#pragma unroll
        for (int dj = 0; dj < 13; dj++) {
            const int jj = tile * 13 + dj;
            if (jj >= 49) break;                      // compile-time
            float pr = acc[jj];
            const float* vb = &Big[(g * 13 + dj) * 36];
#pragma unroll
            for (int cq = 0; cq < 8; cq++) {
                float4 v = *(const float4*)&vb[cq * 4];
                pacc[cq*4+0] += v.x * pr; pacc[cq*4+1] += v.y * pr;
                pacc[cq*4+2] += v.z * pr; pacc[cq*4+3] += v.w * pr;
            }
        }
    }
    // ---- reduce pacc over 16 g via smem, 2 chunks of 16 channels ----
#pragma unroll
    for (int ch = 0; ch < 2; ch++) {
        __syncthreads();
#pragma unroll
        for (int cc = 0; cc < 16; cc++)
            Big[t * 17 + cc] = pacc[ch * 16 + cc];   // stride 17: conflict-free scalar
        __syncthreads();
        int rr = t >> 4, cc = t & 15;
        float s = 0.f;
#pragma unroll
        for (int gg = 0; gg < 16; gg++)
            s += Big[(gg * 16 + rr) * 17 + cc];
        g_dvatt[((long)b * 256 + h * 32 + ch * 16 + cc) * DEMO_TOK + itile * 16 + rr] = s;
    }
}

// ---------------- fused obs attention: scores + softmax + AV (k-split) ----------------
__global__ __launch_bounds__(256, 2) void k_obs_fused(float* __restrict__ part) {
    extern __shared__ float smem[];
    float* Ps = smem;              // [64][200]
    float* Qs = smem + 12800;      // [32][4][52]
    float* KV = smem + 19456;      // Ks[32][64] (phase A) / Vt[64][36] (phase B)
    const int z = blockIdx.x;                  // b*96 + tt*8 + h
    const int khalf = blockIdx.y;
    const int b = z / 96, tt = (z >> 3) % 12, h = z & 7;
    const int t = threadIdx.x;
    const float* Kd = g_dk    + ((long)b * 256 + h * 32) * DEMO_TOK;
    const float* Ko = g_ok    + ((long)b * 256 + h * 32) * OBS_TOK + tt * 196;
    const float* Vd = g_dvatt + ((long)b * 256 + h * 32) * DEMO_TOK;
    const float* Vo = g_ov    + ((long)b * 256 + h * 32) * OBS_TOK + tt * 196;
    const float* Qp = g_oq    + ((long)b * 256 + h * 32) * OBS_TOK + tt * 196;

    for (int e = t; e < 6272; e += 256) {
        int c = e / 196, j = e - c * 196;
        Qs[c * 208 + (j / 49) * 52 + (j % 49)] = Qp[(long)c * OBS_TOK + j];
    }
    const int r = t >> 2, gq = t & 3;
    const int w = t >> 5, jg = t & 31;
    const bool has7 = (jg < 4);
    const int kbase = khalf * 490;
    float out[4][7];
#pragma unroll
    for (int cc = 0; cc < 4; cc++)
#pragma unroll
        for (int q = 0; q < 7; q++) out[cc][q] = 0.f;

    for (int kt = 0; kt < 8; kt++) {
        const int k0 = kbase + kt * 64;
        __syncthreads();
        for (int e = t; e < 2048; e += 256) {
            int c = e >> 6, ii = e & 63;
            int kl = kt * 64 + ii, kg = k0 + ii;
            float v = 0.f;
            if (kl < 490)
                v = (kg < DEMO_TOK) ? Kd[(long)c * DEMO_TOK + kg]
                                    : Ko[(long)c * OBS_TOK + (kg - DEMO_TOK)];
            KV[c * 64 + ii] = v;
        }
        __syncthreads();
        float acc[49];
#pragma unroll
        for (int jj = 0; jj < 49; jj++) acc[jj] = 0.f;
#pragma unroll
        for (int c = 0; c < 32; c++) {
            float a = KV[c * 64 + r];
            const float* q = &Qs[c * 208 + gq * 52];
#pragma unroll
            for (int v = 0; v < 12; v++) {
                float4 qq = *(const float4*)(q + v * 4);
                acc[v*4+0] += a * qq.x; acc[v*4+1] += a * qq.y;
                acc[v*4+2] += a * qq.z; acc[v*4+3] += a * qq.w;
            }
            acc[48] += a * q[48];
        }
        float mx = -1e30f;
#pragma unroll
        for (int jj = 0; jj < 49; jj++) { acc[jj] *= INV_TEMP; mx = fmaxf(mx, acc[jj]); }
        mx = fmaxf(mx, __shfl_xor_sync(0xffffffffu, mx, 1));
        mx = fmaxf(mx, __shfl_xor_sync(0xffffffffu, mx, 2));
        float sm = 0.f;
#pragma unroll
        for (int jj = 0; jj < 49; jj++) { float p = __expf(acc[jj] - mx); acc[jj] = p; sm += p; }
        sm += __shfl_xor_sync(0xffffffffu, sm, 1);
        sm += __shfl_xor_sync(0xffffffffu, sm, 2);
        float inv = 1.f / sm;
        {
            float* pr = &Ps[r * 200 + gq * 49];
#pragma unroll
            for (int jj = 0; jj < 49; jj++) pr[jj] = acc[jj] * inv;
        }
        __syncthreads();
        for (int e = t; e < 2048; e += 256) {
            int c = e >> 6, ii = e & 63;
            int kl = kt * 64 + ii, kg = k0 + ii;
            float v = 0.f;
            if (kl < 490)
                v = (kg < DEMO_TOK) ? Vd[(long)c * DEMO_TOK + kg]
                                    : Vo[(long)c * OBS_TOK + (kg - DEMO_TOK)];
            KV[ii * 36 + c] = v;
        }
        __syncthreads();
#pragma unroll 4
        for (int k = 0; k < 64; k++) {
            float4 v4 = *(const float4*)&KV[k * 36 + w * 4];
            const float* pr = &Ps[k * 200 + jg];
            float p0 = pr[0],  p1 = pr[32], p2 = pr[64];
            float p3 = pr[96], p4 = pr[128], p5 = pr[160];
            float p6 = has7 ? pr[192] : 0.f;
            out[0][0] += v4.x*p0; out[1][0] += v4.y*p0; out[2][0] += v4.z*p0; out[3][0] += v4.w*p0;
            out[0][1] += v4.x*p1; out[1][1] += v4.y*p1; out[2][1] += v4.z*p1; out[3][1] += v4.w*p1;
            out[0][2] += v4.x*p2; out[1][2] += v4.y*p2; out[2][2] += v4.z*p2; out[3][2] += v4.w*p2;
            out[0][3] += v4.x*p3; out[1][3] += v4.y*p3; out[2][3] += v4.z*p3; out[3][3] += v4.w*p3;
            out[0][4] += v4.x*p4; out[1][4] += v4.y*p4; out[2][4] += v4.z*p4; out[3][4] += v4.w*p4;
            out[0][5] += v4.x*p5; out[1][5] += v4.y*p5; out[2][5] += v4.z*p5; out[3][5] += v4.w*p5;
            out[0][6] += v4.x*p6; out[1][6] += v4.y*p6; out[2][6] += v4.z*p6; out[3][6] += v4.w*p6;
        }
    }
    float* op = part + ((long)(khalf * 384 + z)) * 6272;
#pragma unroll
    for (int cc = 0; cc < 4; cc++)
#pragma unroll
        for (int q = 0; q < 7; q++) {
            int j = jg + 32 * q;
            if (j < 196) op[(w * 4 + cc) * 196 + j] = out[cc][q];
        }
}

// ---------------- merge obs AV partials into g_mg (conv layout) ----------------
__global__ void k_merge(const float* __restrict__ part) {
    int z = blockIdx.y;
    int e = blockIdx.x * 256 + threadIdx.x;
    if (e >= 6272) return;
    int c = e / 196, j = e - c * 196;
    int b = z / 96, tt = (z >> 3) % 12, h = z & 7;
    float v = part[(long)z * 6272 + e] + part[(long)(384 + z) * 6272 + e];
    g_mg[((long)b * 256 + h * 32 + c) * OBS_TOK + tt * 196 + j] = v;
}

// ---------------- BatchNorm stats ----------------
__global__ void k_bnstats() {
    const int c = blockIdx.x;
    float s = 0.f, s2 = 0.f;
    for (int e = threadIdx.x; e < BB * THW; e += 256) {
        int b = e / THW, k = e - b * THW;
        float v = g_x[(long)b * CTHW + (long)c * THW + k];
        s += v; s2 += v * v;
    }
#pragma unroll
    for (int o = 16; o; o >>= 1) {
        s  += __shfl_xor_sync(0xffffffffu, s, o);
        s2 += __shfl_xor_sync(0xffffffffu, s2, o);
    }
    __shared__ float ws[8], ws2[8];
    int w = threadIdx.x >> 5;
    if ((threadIdx.x & 31) == 0) { ws[w] = s; ws2[w] = s2; }
    __syncthreads();
    if (threadIdx.x == 0) {
        float S = 0.f, S2 = 0.f;
#pragma unroll
        for (int i = 0; i < 8; i++) { S += ws[i]; S2 += ws2[i]; }
        float m = S * (1.f / 12544.f);
        float var = S2 * (1.f / 12544.f) - m * m;
        g_mean[c] = m;
        g_istd[c] = rsqrtf(var + EPSV);
    }
}

// ---------------- BatchNorm apply ----------------
__global__ void k_bnapply(const float* __restrict__ gamma, const float* __restrict__ beta,
                          float* __restrict__ out) {
    int e = blockIdx.x * 256 + threadIdx.x;   // 802816 float4 over full tensor
    int c = (e / 784) & 255;
    float4 v = ((const float4*)g_x)[e];
    float a = gamma[c] * g_istd[c];
    float b2 = beta[c] - g_mean[c] * a;
    v.x = v.x * a + b2; v.y = v.y * a + b2; v.z = v.z * a + b2; v.w = v.w * a + b2;
    ((float4*)out)[e] = v;
}

// ---------------- host orchestration ----------------
extern "C" void kernel_launch(void* const* d_in, const int* in_sizes, int n_in,
                              void* d_out, int out_size) {
    const float* x    = (const float*)d_in[0];
    const float* w_dq = (const float*)d_in[1];
    const float* w_dk = (const float*)d_in[2];
    const float* w_dv = (const float*)d_in[3];
    const float* w_oq = (const float*)d_in[4];
    const float* w_ok = (const float*)d_in[5];
    const float* w_ov = (const float*)d_in[6];
    const float* w_oo = (const float*)d_in[7];
    const float* gam  = (const float*)d_in[8];
    const float* bet  = (const float*)d_in[9];
    float* out = (float*)d_out;

    float *p_x, *p_dq, *p_dk, *p_dv, *p_oq, *p_ok, *p_ov, *p_mg, *p_part;
    cudaGetSymbolAddress((void**)&p_x,  g_x);
    cudaGetSymbolAddress((void**)&p_dq, g_dq);
    cudaGetSymbolAddress((void**)&p_dk, g_dk);
    cudaGetSymbolAddress((void**)&p_dv, g_dv);
    cudaGetSymbolAddress((void**)&p_oq, g_oq);
    cudaGetSymbolAddress((void**)&p_ok, g_ok);
    cudaGetSymbolAddress((void**)&p_ov, g_ov);
    cudaGetSymbolAddress((void**)&p_mg, g_mg);
    cudaGetSymbolAddress((void**)&p_part, g_part);

    cudaFuncSetAttribute(k_obs_fused, cudaFuncAttributeMaxDynamicSharedMemorySize, 87040);

    k_copy<<<3136, 256>>>((const float4*)x);

    const long xbs = (long)CTHW;
    const long dbs = (long)256 * DEMO_TOK;
    const long obs = (long)256 * OBS_TOK;
    dim3 cg_demo(13, 12, BB), cg_obs(37, 12, BB), cg_out(37, 4, BB);

    for (int l = 0; l < 3; l++) {
        const int WO = l * 256 * 256;
        k_conv3<<<cg_demo, 256>>>(w_dq + WO, w_dk + WO, w_dv + WO,
                                  p_x, THW, 0, xbs,
                                  p_dq, p_dk, p_dv, DEMO_TOK, 0, dbs, DEMO_TOK, 0);
        k_conv3<<<cg_obs, 256>>>(w_oq + WO, w_ok + WO, w_ov + WO,
                                 p_x, THW, DEMO_TOK, xbs,
                                 p_oq, p_ok, p_ov, OBS_TOK, 0, obs, OBS_TOK, 0);
        k_demo_fused<<<dim3(49, 32), 256>>>();
        k_obs_fused<<<dim3(384, 2), 256, 87040>>>(p_part);
        k_merge<<<dim3(25, 384), 256>>>(p_part);
        k_conv3<<<cg_out, 256>>>(w_oo + WO, w_oo + WO, w_oo + WO,
                                 p_mg, OBS_TOK, 0, obs,
                                 p_x, p_x, p_x, THW, DEMO_TOK, xbs, OBS_TOK, 1);
        k_bnstats<<<256, 256>>>();
        k_bnapply<<<3136, 256>>>(gam + l * 256, bet + l * 256, (l == 2) ? out : p_x);
    }
}

// round 8
// speedup vs baseline: 1.9013x; 1.0705x over previous
#include <cuda_runtime.h>
#include <cstdint>

// ---------------- problem constants ----------------
#define BB 4
#define THW 3136          // 16*14*14
#define DEMO_TOK 784
#define OBS_TOK 2352
#define INV_TEMP 0.0625f  // 1/sqrt(256)
#define EPSV 1e-5f
#define CTHW (256*THW)    // 802816

// ---------------- scratch (device globals; allocation-free) ----------------
__device__ __align__(256) float g_x[BB*CTHW];
__device__ __align__(256) float g_dq[BB*256*DEMO_TOK];
__device__ __align__(256) float g_dk[BB*256*DEMO_TOK];
__device__ __align__(256) float g_dv[BB*256*DEMO_TOK];
__device__ __align__(256) float g_dvatt[BB*256*DEMO_TOK];
__device__ __align__(256) float g_oq[BB*256*OBS_TOK];
__device__ __align__(256) float g_ok[BB*256*OBS_TOK];
__device__ __align__(256) float g_ov[BB*256*OBS_TOK];
__device__ __align__(256) float g_mg[BB*256*OBS_TOK];
__device__ __align__(256) float g_part[2*384*32*196];   // obs AV partials (k-split)
__device__ float g_mean[256];
__device__ float g_istd[256];

// ---------------- cp.async helpers ----------------
__device__ __forceinline__ void cp_async16(uint32_t dst, const void* src, int bytes) {
    asm volatile("cp.async.cg.shared.global [%0], [%1], 16, %2;\n"
                 :: "r"(dst), "l"(src), "r"(bytes));
}
__device__ __forceinline__ void cp_commit() {
    asm volatile("cp.async.commit_group;\n");
}
template<int N> __device__ __forceinline__ void cp_wait() {
    asm volatile("cp.async.wait_group %0;\n" :: "n"(N));
}

// ---------------- copy input -> g_x ----------------
// total = BB*CTHW = 3,211,264 floats = 802,816 float4 -> 3136 blocks x 256 thr
__global__ void k_copy(const float4* __restrict__ src) {
    int e = blockIdx.x * 256 + threadIdx.x;
    ((float4*)g_x)[e] = src[e];
}

// ---------------- fused triple 1x1-conv GEMM, cp.async double-buffered ----------------
// grid.y: 12 tiles (qkv) or 4 tiles (single W). sel = my>>2 picks W/O.
// O = W(256x256) * X(256xN); fuse=1: O += relu(acc)
// A smem layout [m(64)][k(32)+pad->36]; B smem [k(32)][n(64)]. 8 k-stages of 32.
__global__ __launch_bounds__(256) void k_conv3(
    const float* __restrict__ W0, const float* __restrict__ W1, const float* __restrict__ W2,
    const float* __restrict__ X, int ldx, int xoff, long xbstr,
    float* __restrict__ O0, float* __restrict__ O1, float* __restrict__ O2,
    int ldo, int ooff, long obstr, int N, int fuse)
{
    __shared__ float As[2][64*36];
    __shared__ float Bs[2][32*64];
    const int t  = threadIdx.x;
    const int b  = blockIdx.z;
    const int my = blockIdx.y;
    const int sel = my >> 2;
    const int m0  = (my & 3) * 64;
    const int n0  = blockIdx.x * 64;
    const float* W = (sel == 0) ? W0 : ((sel == 1) ? W1 : W2);
    float* Obase   = (sel == 0) ? O0 : ((sel == 1) ? O1 : O2);
    const float* Xb = X + b * xbstr + xoff;
    const int ty = t >> 4, tx = t & 15;

    // per-thread copy coordinates
    const int am = t >> 3, aq = t & 7;    // A: rows am, am+32; k-quad aq
    const int bk = t >> 4, bn = t & 15;   // B: rows bk, bk+16; n-quad bn
    const int ncol = n0 + bn * 4;
    const int bbytes = (ncol + 4 <= N) ? 16 : 0;
    const float* asrc0 = &W[(m0 + am) * 256 + aq * 4];
    const float* asrc1 = asrc0 + 32 * 256;
    const float* bsrc  = Xb + (long)bk * ldx + (bbytes ? ncol : n0);
    uint32_t asb = (uint32_t)__cvta_generic_to_shared(&As[0][0]);
    uint32_t bsb = (uint32_t)__cvta_generic_to_shared(&Bs[0][0]);
    const uint32_t ad0 = asb + (uint32_t)((am * 36 + aq * 4) * 4);
    const uint32_t ad1 = asb + (uint32_t)(((am + 32) * 36 + aq * 4) * 4);
    const uint32_t bd0 = bsb + (uint32_t)((bk * 64 + bn * 4) * 4);
    const uint32_t bd1 = bsb + (uint32_t)(((bk + 16) * 64 + bn * 4) * 4);
    const uint32_t ABUF = 64 * 36 * 4, BBUF = 32 * 64 * 4;

#define PREF(K0, S) do { \
    cp_async16(ad0 + (S) * ABUF, asrc0 + (K0) * 32, 16); \
    cp_async16(ad1 + (S) * ABUF, asrc1 + (K0) * 32, 16); \
    cp_async16(bd0 + (S) * BBUF, bsrc + (long)((K0) * 32) * ldx, bbytes); \
    cp_async16(bd1 + (S) * BBUF, bsrc + (long)((K0) * 32 + 16) * ldx, bbytes); \
    cp_commit(); } while (0)

    float acc[4][4];
#pragma unroll
    for (int i = 0; i < 4; i++)
#pragma unroll
        for (int j = 0; j < 4; j++) acc[i][j] = 0.f;

    PREF(0, 0);
    for (int k0 = 0; k0 < 8; k0++) {
        const int cur = k0 & 1;
        if (k0 < 7) { PREF(k0 + 1, cur ^ 1); cp_wait<1>(); }
        else        { cp_wait<0>(); }
        __syncthreads();
        const float* Ac = &As[cur][0];
        const float* Bc = &Bs[cur][0];
#pragma unroll
        for (int k4 = 0; k4 < 8; k4++) {
            float4 a4[4], b4[4];
#pragma unroll
            for (int i = 0; i < 4; i++)
                a4[i] = *(const float4*)&Ac[(ty * 4 + i) * 36 + k4 * 4];
#pragma unroll
            for (int kk = 0; kk < 4; kk++)
                b4[kk] = *(const float4*)&Bc[(k4 * 4 + kk) * 64 + tx * 4];
#pragma unroll
            for (int i = 0; i < 4; i++) {
                acc[i][0] += a4[i].x * b4[0].x; acc[i][1] += a4[i].x * b4[0].y;
                acc[i][2] += a4[i].x * b4[0].z; acc[i][3] += a4[i].x * b4[0].w;
                acc[i][0] += a4[i].y * b4[1].x; acc[i][1] += a4[i].y * b4[1].y;
                acc[i][2] += a4[i].y * b4[1].z; acc[i][3] += a4[i].y * b4[1].w;
                acc[i][0] += a4[i].z * b4[2].x; acc[i][1] += a4[i].z * b4[2].y;
                acc[i][2] += a4[i].z * b4[2].z; acc[i][3] += a4[i].z * b4[2].w;
                acc[i][0] += a4[i].w * b4[3].x; acc[i][1] += a4[i].w * b4[3].y;
                acc[i][2] += a4[i].w * b4[3].z; acc[i][3] += a4[i].w * b4[3].w;
            }
        }
        __syncthreads();
    }
#undef PREF

    float* Ob = Obase + b * obstr + ooff;
#pragma unroll
    for (int i = 0; i < 4; i++) {
        int m = m0 + ty * 4 + i;
#pragma unroll
        for (int j = 0; j < 4; j++) {
            int n = n0 + tx * 4 + j;
            if (n < N) {
                float* p = Ob + (long)m * ldo + n;
                if (fuse) *p = *p + fmaxf(acc[i][j], 0.f);
                else      *p = acc[i][j];
            }
        }
    }
}

// ---------------- fused demo attention: scores + softmax + AV ----------------
// r = t&15 (row), g = t>>4 (j-group): warp spans 2 g values -> broadcast LDS.
// ROUND-7 CHANGE: phase-3 V loader uses lane=dj (13 active lanes, consecutive
// addresses) -> 1 LDG wavefront per instr instead of 8.
__global__ __launch_bounds__(256, 2) void k_demo_fused() {
    const int t = threadIdx.x;
    const int itile = blockIdx.x;        // 0..48
    const int bh = blockIdx.y;           // 0..31
    const int b = bh >> 3, h = bh & 7;
    const float* Kp = g_dk + ((long)b * 256 + h * 32) * DEMO_TOK;
    const float* Qp = g_dq + ((long)b * 256 + h * 32) * DEMO_TOK;
    const float* Vp = g_dv + ((long)b * 256 + h * 32) * DEMO_TOK;
    __shared__ float Ks[512];            // [c(32)][i(16)]
    __shared__ float Red[256];           // [g(16)][r(16)] reduction staging
    __shared__ float Big[7488];          // phase1: Qs[8][16][52]; phase3: Vt / staging
    const int r = t & 15;                // row within tile
    const int g = t >> 4;                // j-group of 49
    const int wc = t >> 5;               // warp id
    const int ln = t & 31;               // lane
    float acc[49];
#pragma unroll
    for (int jj = 0; jj < 49; jj++) acc[jj] = 0.f;

#pragma unroll
    for (int e = t; e < 512; e += 256) {
        int c = e >> 4, ii = e & 15;
        Ks[c * 16 + ii] = Kp[(long)c * DEMO_TOK + itile * 16 + ii];
    }
    // ---- phase 1: scores ----
    for (int cb = 0; cb < 4; cb++) {
        __syncthreads();
        // div-free Q loader: warp wc owns channel wc; coalesced lanes
        {
            const float* qsrc = Qp + (long)(cb * 8 + wc) * DEMO_TOK;
            float* qdst = &Big[wc * 832];
#pragma unroll
            for (int jq = 0; jq < 16; jq++) {
#pragma unroll
                for (int half = 0; half < 2; half++) {
                    int jr = ln + half * 32;
                    if (jr < 49)
                        qdst[jq * 52 + jr] = qsrc[jq * 49 + jr];
                }
            }
        }
        __syncthreads();
#pragma unroll
        for (int cc = 0; cc < 8; cc++) {
            float a = Ks[(cb * 8 + cc) * 16 + r];
            const float* q = &Big[cc * 832 + g * 52];
#pragma unroll
            for (int v = 0; v < 12; v++) {
                float4 qq = *(const float4*)(q + v * 4);
                acc[v*4+0] += a * qq.x; acc[v*4+1] += a * qq.y;
                acc[v*4+2] += a * qq.z; acc[v*4+3] += a * qq.w;
            }
            acc[48] += a * q[48];
        }
    }
    // ---- phase 2: softmax over j; reduce over 16 g via smem ----
    float mx = -1e30f;
#pragma unroll
    for (int jj = 0; jj < 49; jj++) { acc[jj] *= INV_TEMP; mx = fmaxf(mx, acc[jj]); }
    __syncthreads();
    Red[g * 16 + r] = mx;
    __syncthreads();
    float gm = Red[r];
#pragma unroll
    for (int gg = 1; gg < 16; gg++) gm = fmaxf(gm, Red[gg * 16 + r]);
    __syncthreads();
    float sm = 0.f;
#pragma unroll
    for (int jj = 0; jj < 49; jj++) { float p = __expf(acc[jj] - gm); acc[jj] = p; sm += p; }
    Red[g * 16 + r] = sm;
    __syncthreads();
    float gs = Red[r];
#pragma unroll
    for (int gg = 1; gg < 16; gg++) gs += Red[gg * 16 + r];
    float inv = 1.f / gs;
#pragma unroll
    for (int jj = 0; jj < 49; jj++) acc[jj] *= inv;   // p in registers

    // ---- phase 3: AV. V tiles transposed in smem; coalesced 13-lane loader ----
    float pacc[32];
#pragma unroll
    for (int c = 0; c < 32; c++) pacc[c] = 0.f;
#pragma unroll
    for (int tile = 0; tile < 4; tile++) {
        __syncthreads();
        // Big[(gg*13+dj)*36 + c] = V[c, gg*49 + tile*13 + dj]
        // lane = dj (13 active): each LDG reads 13 consecutive floats (1 wf)
        {
            const int ndj = (tile < 3) ? 13 : 10;
            if (ln < ndj) {
#pragma unroll 16
                for (int it = 0; it < 64; it++) {
                    int c  = wc * 4 + (it >> 4);
                    int gg = it & 15;
                    Big[(gg * 13 + ln) * 36 + c] =
                        Vp[(long)c * DEMO_TOK + gg * 49 + tile * 13 + ln];
                }
            }
        }
        __syncthreads();
#pragma unroll
        for (int dj = 0; dj < 13; dj++) {
            const int jj = tile * 13 + dj;
            if (jj >= 49) break;                      // compile-time
            float pr = acc[jj];
            const float* vb = &Big[(g * 13 + dj) * 36];
#pragma unroll
            for (int cq = 0; cq < 8; cq++) {
                float4 v = *(const float4*)&vb[cq * 4];
                pacc[cq*4+0] += v.x * pr; pacc[cq*4+1] += v.y * pr;
                pacc[cq*4+2] += v.z * pr; pacc[cq*4+3] += v.w * pr;
            }
        }
    }
    // ---- reduce pacc over 16 g via smem, 2 chunks of 16 channels ----
#pragma unroll
    for (int ch = 0; ch < 2; ch++) {
        __syncthreads();
#pragma unroll
        for (int cc = 0; cc < 16; cc++)
            Big[t * 17 + cc] = pacc[ch * 16 + cc];   // stride 17: conflict-free scalar
        __syncthreads();
        int rr = t >> 4, cc = t & 15;
        float s = 0.f;
#pragma unroll
        for (int gg = 0; gg < 16; gg++)
            s += Big[(gg * 16 + rr) * 17 + cc];
        g_dvatt[((long)b * 256 + h * 32 + ch * 16 + cc) * DEMO_TOK + itile * 16 + rr] = s;
    }
}

// ---------------- fused obs attention: scores + softmax + AV (k-split) ----------------
__global__ __launch_bounds__(256, 2) void k_obs_fused(float* __restrict__ part) {
    extern __shared__ float smem[];
    float* Ps = smem;              // [64][200]
    float* Qs = smem + 12800;      // [32][4][52]
    float* KV = smem + 19456;      // Ks[32][64] (phase A) / Vt[64][36] (phase B)
    const int z = blockIdx.x;                  // b*96 + tt*8 + h
    const int khalf = blockIdx.y;
    const int b = z / 96, tt = (z >> 3) % 12, h = z & 7;
    const int t = threadIdx.x;
    const float* Kd = g_dk    + ((long)b * 256 + h * 32) * DEMO_TOK;
    const float* Ko = g_ok    + ((long)b * 256 + h * 32) * OBS_TOK + tt * 196;
    const float* Vd = g_dvatt + ((long)b * 256 + h * 32) * DEMO_TOK;
    const float* Vo = g_ov    + ((long)b * 256 + h * 32) * OBS_TOK + tt * 196;
    const float* Qp = g_oq    + ((long)b * 256 + h * 32) * OBS_TOK + tt * 196;

    for (int e = t; e < 6272; e += 256) {
        int c = e / 196, j = e - c * 196;
        Qs[c * 208 + (j / 49) * 52 + (j % 49)] = Qp[(long)c * OBS_TOK + j];
    }
    const int r = t >> 2, gq = t & 3;
    const int w = t >> 5, jg = t & 31;
    const bool has7 = (jg < 4);
    const int kbase = khalf * 490;
    float out[4][7];
#pragma unroll
    for (int cc = 0; cc < 4; cc++)
#pragma unroll
        for (int q = 0; q < 7; q++) out[cc][q] = 0.f;

    for (int kt = 0; kt < 8; kt++) {
        const int k0 = kbase + kt * 64;
        __syncthreads();
        for (int e = t; e < 2048; e += 256) {
            int c = e >> 6, ii = e & 63;
            int kl = kt * 64 + ii, kg = k0 + ii;
            float v = 0.f;
            if (kl < 490)
                v = (kg < DEMO_TOK) ? Kd[(long)c * DEMO_TOK + kg]
                                    : Ko[(long)c * OBS_TOK + (kg - DEMO_TOK)];
            KV[c * 64 + ii] = v;
        }
        __syncthreads();
        float acc[49];
#pragma unroll
        for (int jj = 0; jj < 49; jj++) acc[jj] = 0.f;
#pragma unroll
        for (int c = 0; c < 32; c++) {
            float a = KV[c * 64 + r];
            const float* q = &Qs[c * 208 + gq * 52];
#pragma unroll
            for (int v = 0; v < 12; v++) {
                float4 qq = *(const float4*)(q + v * 4);
                acc[v*4+0] += a * qq.x; acc[v*4+1] += a * qq.y;
                acc[v*4+2] += a * qq.z; acc[v*4+3] += a * qq.w;
            }
            acc[48] += a * q[48];
        }
        float mx = -1e30f;
#pragma unroll
        for (int jj = 0; jj < 49; jj++) { acc[jj] *= INV_TEMP; mx = fmaxf(mx, acc[jj]); }
        mx = fmaxf(mx, __shfl_xor_sync(0xffffffffu, mx, 1));
        mx = fmaxf(mx, __shfl_xor_sync(0xffffffffu, mx, 2));
        float sm = 0.f;
#pragma unroll
        for (int jj = 0; jj < 49; jj++) { float p = __expf(acc[jj] - mx); acc[jj] = p; sm += p; }
        sm += __shfl_xor_sync(0xffffffffu, sm, 1);
        sm += __shfl_xor_sync(0xffffffffu, sm, 2);
        float inv = 1.f / sm;
        {
            float* pr = &Ps[r * 200 + gq * 49];
#pragma unroll
            for (int jj = 0; jj < 49; jj++) pr[jj] = acc[jj] * inv;
        }
        __syncthreads();
        for (int e = t; e < 2048; e += 256) {
            int c = e >> 6, ii = e & 63;
            int kl = kt * 64 + ii, kg = k0 + ii;
            float v = 0.f;
            if (kl < 490)
                v = (kg < DEMO_TOK) ? Vd[(long)c * DEMO_TOK + kg]
                                    : Vo[(long)c * OBS_TOK + (kg - DEMO_TOK)];
            KV[ii * 36 + c] = v;
        }
        __syncthreads();
#pragma unroll 4
        for (int k = 0; k < 64; k++) {
            float4 v4 = *(const float4*)&KV[k * 36 + w * 4];
            const float* pr = &Ps[k * 200 + jg];
            float p0 = pr[0],  p1 = pr[32], p2 = pr[64];
            float p3 = pr[96], p4 = pr[128], p5 = pr[160];
            float p6 = has7 ? pr[192] : 0.f;
            out[0][0] += v4.x*p0; out[1][0] += v4.y*p0; out[2][0] += v4.z*p0; out[3][0] += v4.w*p0;
            out[0][1] += v4.x*p1; out[1][1] += v4.y*p1; out[2][1] += v4.z*p1; out[3][1] += v4.w*p1;
            out[0][2] += v4.x*p2; out[1][2] += v4.y*p2; out[2][2] += v4.z*p2; out[3][2] += v4.w*p2;
            out[0][3] += v4.x*p3; out[1][3] += v4.y*p3; out[2][3] += v4.z*p3; out[3][3] += v4.w*p3;
            out[0][4] += v4.x*p4; out[1][4] += v4.y*p4; out[2][4] += v4.z*p4; out[3][4] += v4.w*p4;
            out[0][5] += v4.x*p5; out[1][5] += v4.y*p5; out[2][5] += v4.z*p5; out[3][5] += v4.w*p5;
            out[0][6] += v4.x*p6; out[1][6] += v4.y*p6; out[2][6] += v4.z*p6; out[3][6] += v4.w*p6;
        }
    }
    float* op = part + ((long)(khalf * 384 + z)) * 6272;
#pragma unroll
    for (int cc = 0; cc < 4; cc++)
#pragma unroll
        for (int q = 0; q < 7; q++) {
            int j = jg + 32 * q;
            if (j < 196) op[(w * 4 + cc) * 196 + j] = out[cc][q];
        }
}

// ---------------- merge obs AV partials into g_mg (conv layout) ----------------
__global__ void k_merge(const float* __restrict__ part) {
    int z = blockIdx.y;
    int e = blockIdx.x * 256 + threadIdx.x;
    if (e >= 6272) return;
    int c = e / 196, j = e - c * 196;
    int b = z / 96, tt = (z >> 3) % 12, h = z & 7;
    float v = part[(long)z * 6272 + e] + part[(long)(384 + z) * 6272 + e];
    g_mg[((long)b * 256 + h * 32 + c) * OBS_TOK + tt * 196 + j] = v;
}

// ---------------- BatchNorm stats ----------------
__global__ void k_bnstats() {
    const int c = blockIdx.x;
    float s = 0.f, s2 = 0.f;
    for (int e = threadIdx.x; e < BB * THW; e += 256) {
        int b = e / THW, k = e - b * THW;
        float v = g_x[(long)b * CTHW + (long)c * THW + k];
        s += v; s2 += v * v;
    }
#pragma unroll
    for (int o = 16; o; o >>= 1) {
        s  += __shfl_xor_sync(0xffffffffu, s, o);
        s2 += __shfl_xor_sync(0xffffffffu, s2, o);
    }
    __shared__ float ws[8], ws2[8];
    int w = threadIdx.x >> 5;
    if ((threadIdx.x & 31) == 0) { ws[w] = s; ws2[w] = s2; }
    __syncthreads();
    if (threadIdx.x == 0) {
        float S = 0.f, S2 = 0.f;
#pragma unroll
        for (int i = 0; i < 8; i++) { S += ws[i]; S2 += ws2[i]; }
        float m = S * (1.f / 12544.f);
        float var = S2 * (1.f / 12544.f) - m * m;
        g_mean[c] = m;
        g_istd[c] = rsqrtf(var + EPSV);
    }
}

// ---------------- BatchNorm apply ----------------
__global__ void k_bnapply(const float* __restrict__ gamma, const float* __restrict__ beta,
                          float* __restrict__ out) {
    int e = blockIdx.x * 256 + threadIdx.x;   // 802816 float4 over full tensor
    int c = (e / 784) & 255;
    float4 v = ((const float4*)g_x)[e];
    float a = gamma[c] * g_istd[c];
    float b2 = beta[c] - g_mean[c] * a;
    v.x = v.x * a + b2; v.y = v.y * a + b2; v.z = v.z * a + b2; v.w = v.w * a + b2;
    ((float4*)out)[e] = v;
}

// ---------------- host orchestration ----------------
extern "C" void kernel_launch(void* const* d_in, const int* in_sizes, int n_in,
                              void* d_out, int out_size) {
    const float* x    = (const float*)d_in[0];
    const float* w_dq = (const float*)d_in[1];
    const float* w_dk = (const float*)d_in[2];
    const float* w_dv = (const float*)d_in[3];
    const float* w_oq = (const float*)d_in[4];
    const float* w_ok = (const float*)d_in[5];
    const float* w_ov = (const float*)d_in[6];
    const float* w_oo = (const float*)d_in[7];
    const float* gam  = (const float*)d_in[8];
    const float* bet  = (const float*)d_in[9];
    float* out = (float*)d_out;

    float *p_x, *p_dq, *p_dk, *p_dv, *p_oq, *p_ok, *p_ov, *p_mg, *p_part;
    cudaGetSymbolAddress((void**)&p_x,  g_x);
    cudaGetSymbolAddress((void**)&p_dq, g_dq);
    cudaGetSymbolAddress((void**)&p_dk, g_dk);
    cudaGetSymbolAddress((void**)&p_dv, g_dv);
    cudaGetSymbolAddress((void**)&p_oq, g_oq);
    cudaGetSymbolAddress((void**)&p_ok, g_ok);
    cudaGetSymbolAddress((void**)&p_ov, g_ov);
    cudaGetSymbolAddress((void**)&p_mg, g_mg);
    cudaGetSymbolAddress((void**)&p_part, g_part);

    cudaFuncSetAttribute(k_obs_fused, cudaFuncAttributeMaxDynamicSharedMemorySize, 87040);

    k_copy<<<3136, 256>>>((const float4*)x);

    const long xbs = (long)CTHW;
    const long dbs = (long)256 * DEMO_TOK;
    const long obs = (long)256 * OBS_TOK;
    dim3 cg_demo(13, 12, BB), cg_obs(37, 12, BB), cg_out(37, 4, BB);

    for (int l = 0; l < 3; l++) {
        const int WO = l * 256 * 256;
        k_conv3<<<cg_demo, 256>>>(w_dq + WO, w_dk + WO, w_dv + WO,
                                  p_x, THW, 0, xbs,
                                  p_dq, p_dk, p_dv, DEMO_TOK, 0, dbs, DEMO_TOK, 0);
        k_conv3<<<cg_obs, 256>>>(w_oq + WO, w_ok + WO, w_ov + WO,
                                 p_x, THW, DEMO_TOK, xbs,
                                 p_oq, p_ok, p_ov, OBS_TOK, 0, obs, OBS_TOK, 0);
        k_demo_fused<<<dim3(49, 32), 256>>>();
        k_obs_fused<<<dim3(384, 2), 256, 87040>>>(p_part);
        k_merge<<<dim3(25, 384), 256>>>(p_part);
        k_conv3<<<cg_out, 256>>>(w_oo + WO, w_oo + WO, w_oo + WO,
                                 p_mg, OBS_TOK, 0, obs,
                                 p_x, p_x, p_x, THW, DEMO_TOK, xbs, OBS_TOK, 1);
        k_bnstats<<<256, 256>>>();
        k_bnapply<<<3136, 256>>>(gam + l * 256, bet + l * 256, (l == 2) ? out : p_x);
    }
}

// round 9
// speedup vs baseline: 1.9026x; 1.0007x over previous
#include <cuda_runtime.h>
#include <cstdint>

// ---------------- problem constants ----------------
#define BB 4
#define THW 3136          // 16*14*14
#define DEMO_TOK 784
#define OBS_TOK 2352
#define INV_TEMP 0.0625f  // 1/sqrt(256)
#define EPSV 1e-5f
#define CTHW (256*THW)    // 802816

// ---------------- scratch (device globals; allocation-free) ----------------
__device__ __align__(256) float g_x[BB*CTHW];
__device__ __align__(256) float g_dq[BB*256*DEMO_TOK];
__device__ __align__(256) float g_dk[BB*256*DEMO_TOK];
__device__ __align__(256) float g_dv[BB*256*DEMO_TOK];
__device__ __align__(256) float g_dvatt[BB*256*DEMO_TOK];
__device__ __align__(256) float g_oq[BB*256*OBS_TOK];
__device__ __align__(256) float g_ok[BB*256*OBS_TOK];
__device__ __align__(256) float g_ov[BB*256*OBS_TOK];
__device__ __align__(256) float g_mg[BB*256*OBS_TOK];
__device__ __align__(256) float g_part[2*384*32*196];   // obs AV partials (k-split)
__device__ float g_mean[256];
__device__ float g_istd[256];

// ---------------- packed f32x2 helpers (Blackwell FFMA2 path) ----------------
__device__ __forceinline__ unsigned long long pk2(float x) {
    unsigned long long r;
    asm("mov.b64 %0, {%1, %1};" : "=l"(r) : "f"(x));
    return r;
}
__device__ __forceinline__ unsigned long long fma2(
    unsigned long long a, unsigned long long b, unsigned long long c) {
    unsigned long long d;
    asm("fma.rn.f32x2 %0, %1, %2, %3;" : "=l"(d) : "l"(a), "l"(b), "l"(c));
    return d;
}
__device__ __forceinline__ float2 upk(unsigned long long v) {
    float2 f;
    asm("mov.b64 {%0, %1}, %2;" : "=f"(f.x), "=f"(f.y) : "l"(v));
    return f;
}

// ---------------- cp.async helpers ----------------
__device__ __forceinline__ void cp_async16(uint32_t dst, const void* src, int bytes) {
    asm volatile("cp.async.cg.shared.global [%0], [%1], 16, %2;\n"
                 :: "r"(dst), "l"(src), "r"(bytes));
}
__device__ __forceinline__ void cp_commit() {
    asm volatile("cp.async.commit_group;\n");
}
template<int N> __device__ __forceinline__ void cp_wait() {
    asm volatile("cp.async.wait_group %0;\n" :: "n"(N));
}

// ---------------- copy input -> g_x ----------------
__global__ void k_copy(const float4* __restrict__ src) {
    int e = blockIdx.x * 256 + threadIdx.x;
    ((float4*)g_x)[e] = src[e];
}

// ---------------- fused triple 1x1-conv GEMM, cp.async + FFMA2 ----------------
__global__ __launch_bounds__(256) void k_conv3(
    const float* __restrict__ W0, const float* __restrict__ W1, const float* __restrict__ W2,
    const float* __restrict__ X, int ldx, int xoff, long xbstr,
    float* __restrict__ O0, float* __restrict__ O1, float* __restrict__ O2,
    int ldo, int ooff, long obstr, int N, int fuse)
{
    __shared__ float As[2][64*36];
    __shared__ float Bs[2][32*64];
    const int t  = threadIdx.x;
    const int b  = blockIdx.z;
    const int my = blockIdx.y;
    const int sel = my >> 2;
    const int m0  = (my & 3) * 64;
    const int n0  = blockIdx.x * 64;
    const float* W = (sel == 0) ? W0 : ((sel == 1) ? W1 : W2);
    float* Obase   = (sel == 0) ? O0 : ((sel == 1) ? O1 : O2);
    const float* Xb = X + b * xbstr + xoff;
    const int ty = t >> 4, tx = t & 15;

    const int am = t >> 3, aq = t & 7;
    const int bk = t >> 4, bn = t & 15;
    const int ncol = n0 + bn * 4;
    const int bbytes = (ncol + 4 <= N) ? 16 : 0;
    const float* asrc0 = &W[(m0 + am) * 256 + aq * 4];
    const float* asrc1 = asrc0 + 32 * 256;
    const float* bsrc  = Xb + (long)bk * ldx + (bbytes ? ncol : n0);
    uint32_t asb = (uint32_t)__cvta_generic_to_shared(&As[0][0]);
    uint32_t bsb = (uint32_t)__cvta_generic_to_shared(&Bs[0][0]);
    const uint32_t ad0 = asb + (uint32_t)((am * 36 + aq * 4) * 4);
    const uint32_t ad1 = asb + (uint32_t)(((am + 32) * 36 + aq * 4) * 4);
    const uint32_t bd0 = bsb + (uint32_t)((bk * 64 + bn * 4) * 4);
    const uint32_t bd1 = bsb + (uint32_t)(((bk + 16) * 64 + bn * 4) * 4);
    const uint32_t ABUF = 64 * 36 * 4, BBUF = 32 * 64 * 4;

#define PREF(K0, S) do { \
    cp_async16(ad0 + (S) * ABUF, asrc0 + (K0) * 32, 16); \
    cp_async16(ad1 + (S) * ABUF, asrc1 + (K0) * 32, 16); \
    cp_async16(bd0 + (S) * BBUF, bsrc + (long)((K0) * 32) * ldx, bbytes); \
    cp_async16(bd1 + (S) * BBUF, bsrc + (long)((K0) * 32 + 16) * ldx, bbytes); \
    cp_commit(); } while (0)

    unsigned long long acc2[4][2];
#pragma unroll
    for (int i = 0; i < 4; i++) { acc2[i][0] = 0ull; acc2[i][1] = 0ull; }

    PREF(0, 0);
    for (int k0 = 0; k0 < 8; k0++) {
        const int cur = k0 & 1;
        if (k0 < 7) { PREF(k0 + 1, cur ^ 1); cp_wait<1>(); }
        else        { cp_wait<0>(); }
        __syncthreads();
        const float* Ac = &As[cur][0];
        const float* Bc = &Bs[cur][0];
#pragma unroll
        for (int k4 = 0; k4 < 8; k4++) {
            float4 a4[4]; ulonglong2 b2[4];
#pragma unroll
            for (int i = 0; i < 4; i++)
                a4[i] = *(const float4*)&Ac[(ty * 4 + i) * 36 + k4 * 4];
#pragma unroll
            for (int kk = 0; kk < 4; kk++)
                b2[kk] = *(const ulonglong2*)&Bc[(k4 * 4 + kk) * 64 + tx * 4];
#pragma unroll
            for (int kk = 0; kk < 4; kk++) {
#pragma unroll
                for (int i = 0; i < 4; i++) {
                    float av = (kk == 0) ? a4[i].x : (kk == 1) ? a4[i].y
                             : (kk == 2) ? a4[i].z : a4[i].w;
                    unsigned long long aa = pk2(av);
                    acc2[i][0] = fma2(aa, b2[kk].x, acc2[i][0]);
                    acc2[i][1] = fma2(aa, b2[kk].y, acc2[i][1]);
                }
            }
        }
        __syncthreads();
    }
#undef PREF

    float* Ob = Obase + b * obstr + ooff;
#pragma unroll
    for (int i = 0; i < 4; i++) {
        int m = m0 + ty * 4 + i;
        float2 p0 = upk(acc2[i][0]), p1 = upk(acc2[i][1]);
        float accf[4] = {p0.x, p0.y, p1.x, p1.y};
#pragma unroll
        for (int j = 0; j < 4; j++) {
            int n = n0 + tx * 4 + j;
            if (n < N) {
                float* p = Ob + (long)m * ldo + n;
                if (fuse) *p = *p + fmaxf(accf[j], 0.f);
                else      *p = accf[j];
            }
        }
    }
}

// ---------------- fused demo attention: scores + softmax + AV (FFMA2) ----------------
__global__ __launch_bounds__(256, 2) void k_demo_fused() {
    const int t = threadIdx.x;
    const int itile = blockIdx.x;        // 0..48
    const int bh = blockIdx.y;           // 0..31
    const int b = bh >> 3, h = bh & 7;
    const float* Kp = g_dk + ((long)b * 256 + h * 32) * DEMO_TOK;
    const float* Qp = g_dq + ((long)b * 256 + h * 32) * DEMO_TOK;
    const float* Vp = g_dv + ((long)b * 256 + h * 32) * DEMO_TOK;
    __shared__ float Ks[512];            // [c(32)][i(16)]
    __shared__ float Red[256];           // [g(16)][r(16)]
    __shared__ float Big[7488];          // Qs[8][16][52] / Vt / staging
    const int r = t & 15;
    const int g = t >> 4;
    const int wc = t >> 5;
    const int ln = t & 31;
    unsigned long long acc2[24];
    float acc48 = 0.f;
#pragma unroll
    for (int p = 0; p < 24; p++) acc2[p] = 0ull;

#pragma unroll
    for (int e = t; e < 512; e += 256) {
        int c = e >> 4, ii = e & 15;
        Ks[c * 16 + ii] = Kp[(long)c * DEMO_TOK + itile * 16 + ii];
    }
    // ---- phase 1: scores (packed) ----
    for (int cb = 0; cb < 4; cb++) {
        __syncthreads();
        {
            const float* qsrc = Qp + (long)(cb * 8 + wc) * DEMO_TOK;
            float* qdst = &Big[wc * 832];
#pragma unroll
            for (int jq = 0; jq < 16; jq++) {
#pragma unroll
                for (int half = 0; half < 2; half++) {
                    int jr = ln + half * 32;
                    if (jr < 49)
                        qdst[jq * 52 + jr] = qsrc[jq * 49 + jr];
                }
            }
        }
        __syncthreads();
#pragma unroll
        for (int cc = 0; cc < 8; cc++) {
            float a = Ks[(cb * 8 + cc) * 16 + r];
            unsigned long long aa = pk2(a);
            const ulonglong2* q2 = (const ulonglong2*)&Big[cc * 832 + g * 52];
#pragma unroll
            for (int v = 0; v < 12; v++) {
                ulonglong2 qq = q2[v];
                acc2[v*2+0] = fma2(aa, qq.x, acc2[v*2+0]);
                acc2[v*2+1] = fma2(aa, qq.y, acc2[v*2+1]);
            }
            acc48 += a * Big[cc * 832 + g * 52 + 48];
        }
    }
    // ---- phase 2: unpack + softmax over j; reduce over 16 g via smem ----
    float acc[49];
#pragma unroll
    for (int p = 0; p < 24; p++) {
        float2 f = upk(acc2[p]);
        acc[p*2] = f.x; acc[p*2+1] = f.y;
    }
    acc[48] = acc48;
    float mx = -1e30f;
#pragma unroll
    for (int jj = 0; jj < 49; jj++) { acc[jj] *= INV_TEMP; mx = fmaxf(mx, acc[jj]); }
    __syncthreads();
    Red[g * 16 + r] = mx;
    __syncthreads();
    float gm = Red[r];
#pragma unroll
    for (int gg = 1; gg < 16; gg++) gm = fmaxf(gm, Red[gg * 16 + r]);
    __syncthreads();
    float sm = 0.f;
#pragma unroll
    for (int jj = 0; jj < 49; jj++) { float p = __expf(acc[jj] - gm); acc[jj] = p; sm += p; }
    Red[g * 16 + r] = sm;
    __syncthreads();
    float gs = Red[r];
#pragma unroll
    for (int gg = 1; gg < 16; gg++) gs += Red[gg * 16 + r];
    float inv = 1.f / gs;
#pragma unroll
    for (int jj = 0; jj < 49; jj++) acc[jj] *= inv;

    // ---- phase 3: AV (packed), coalesced 13-lane loader ----
    unsigned long long pacc2[16];
#pragma unroll
    for (int p = 0; p < 16; p++) pacc2[p] = 0ull;
#pragma unroll
    for (int tile = 0; tile < 4; tile++) {
        __syncthreads();
        {
            const int ndj = (tile < 3) ? 13 : 10;
            if (ln < ndj) {
#pragma unroll 16
                for (int it = 0; it < 64; it++) {
                    int c  = wc * 4 + (it >> 4);
                    int gg = it & 15;
                    Big[(gg * 13 + ln) * 36 + c] =
                        Vp[(long)c * DEMO_TOK + gg * 49 + tile * 13 + ln];
                }
            }
        }
        __syncthreads();
#pragma unroll
        for (int dj = 0; dj < 13; dj++) {
            const int jj = tile * 13 + dj;
            if (jj >= 49) break;
            unsigned long long pp = pk2(acc[jj]);
            const ulonglong2* vb2 = (const ulonglong2*)&Big[(g * 13 + dj) * 36];
#pragma unroll
            for (int u = 0; u < 8; u++) {
                ulonglong2 v = vb2[u];
                pacc2[u*2+0] = fma2(v.x, pp, pacc2[u*2+0]);
                pacc2[u*2+1] = fma2(v.y, pp, pacc2[u*2+1]);
            }
        }
    }
    float pacc[32];
#pragma unroll
    for (int p = 0; p < 16; p++) {
        float2 f = upk(pacc2[p]);
        pacc[p*2] = f.x; pacc[p*2+1] = f.y;
    }
#pragma unroll
    for (int ch = 0; ch < 2; ch++) {
        __syncthreads();
#pragma unroll
        for (int cc = 0; cc < 16; cc++)
            Big[t * 17 + cc] = pacc[ch * 16 + cc];
        __syncthreads();
        int rr = t >> 4, cc = t & 15;
        float s = 0.f;
#pragma unroll
        for (int gg = 0; gg < 16; gg++)
            s += Big[(gg * 16 + rr) * 17 + cc];
        g_dvatt[((long)b * 256 + h * 32 + ch * 16 + cc) * DEMO_TOK + itile * 16 + rr] = s;
    }
}

// ---------------- fused obs attention: scores + softmax + AV (k-split, FFMA2) ----------------
__global__ __launch_bounds__(256, 2) void k_obs_fused(float* __restrict__ part) {
    extern __shared__ float smem[];
    float* Ps = smem;              // [64][200]
    float* Qs = smem + 12800;      // [32][4][52]
    float* KV = smem + 19456;      // Ks[32][64] / Vt[64][36]
    const int z = blockIdx.x;
    const int khalf = blockIdx.y;
    const int b = z / 96, tt = (z >> 3) % 12, h = z & 7;
    const int t = threadIdx.x;
    const float* Kd = g_dk    + ((long)b * 256 + h * 32) * DEMO_TOK;
    const float* Ko = g_ok    + ((long)b * 256 + h * 32) * OBS_TOK + tt * 196;
    const float* Vd = g_dvatt + ((long)b * 256 + h * 32) * DEMO_TOK;
    const float* Vo = g_ov    + ((long)b * 256 + h * 32) * OBS_TOK + tt * 196;
    const float* Qp = g_oq    + ((long)b * 256 + h * 32) * OBS_TOK + tt * 196;

    for (int e = t; e < 6272; e += 256) {
        int c = e / 196, j = e - c * 196;
        Qs[c * 208 + (j / 49) * 52 + (j % 49)] = Qp[(long)c * OBS_TOK + j];
    }
    const int r = t >> 2, gq = t & 3;
    const int w = t >> 5, jg = t & 31;
    const bool has7 = (jg < 4);
    const int kbase = khalf * 490;
    unsigned long long out2[2][7];
#pragma unroll
    for (int cc = 0; cc < 2; cc++)
#pragma unroll
        for (int q = 0; q < 7; q++) out2[cc][q] = 0ull;

    for (int kt = 0; kt < 8; kt++) {
        const int k0 = kbase + kt * 64;
        __syncthreads();
        for (int e = t; e < 2048; e += 256) {
            int c = e >> 6, ii = e & 63;
            int kl = kt * 64 + ii, kg = k0 + ii;
            float v = 0.f;
            if (kl < 490)
                v = (kg < DEMO_TOK) ? Kd[(long)c * DEMO_TOK + kg]
                                    : Ko[(long)c * OBS_TOK + (kg - DEMO_TOK)];
            KV[c * 64 + ii] = v;
        }
        __syncthreads();
        // scores (packed)
        unsigned long long acc2[24];
        float acc48 = 0.f;
#pragma unroll
        for (int p = 0; p < 24; p++) acc2[p] = 0ull;
#pragma unroll
        for (int c = 0; c < 32; c++) {
            float a = KV[c * 64 + r];
            unsigned long long aa = pk2(a);
            const ulonglong2* q2 = (const ulonglong2*)&Qs[c * 208 + gq * 52];
#pragma unroll
            for (int v = 0; v < 12; v++) {
                ulonglong2 qq = q2[v];
                acc2[v*2+0] = fma2(aa, qq.x, acc2[v*2+0]);
                acc2[v*2+1] = fma2(aa, qq.y, acc2[v*2+1]);
            }
            acc48 += a * Qs[c * 208 + gq * 52 + 48];
        }
        float acc[49];
#pragma unroll
        for (int p = 0; p < 24; p++) {
            float2 f = upk(acc2[p]);
            acc[p*2] = f.x; acc[p*2+1] = f.y;
        }
        acc[48] = acc48;
        float mx = -1e30f;
#pragma unroll
        for (int jj = 0; jj < 49; jj++) { acc[jj] *= INV_TEMP; mx = fmaxf(mx, acc[jj]); }
        mx = fmaxf(mx, __shfl_xor_sync(0xffffffffu, mx, 1));
        mx = fmaxf(mx, __shfl_xor_sync(0xffffffffu, mx, 2));
        float sm = 0.f;
#pragma unroll
        for (int jj = 0; jj < 49; jj++) { float p = __expf(acc[jj] - mx); acc[jj] = p; sm += p; }
        sm += __shfl_xor_sync(0xffffffffu, sm, 1);
        sm += __shfl_xor_sync(0xffffffffu, sm, 2);
        float inv = 1.f / sm;
        {
            float* pr = &Ps[r * 200 + gq * 49];
#pragma unroll
            for (int jj = 0; jj < 49; jj++) pr[jj] = acc[jj] * inv;
        }
        __syncthreads();
        for (int e = t; e < 2048; e += 256) {
            int c = e >> 6, ii = e & 63;
            int kl = kt * 64 + ii, kg = k0 + ii;
            float v = 0.f;
            if (kl < 490)
                v = (kg < DEMO_TOK) ? Vd[(long)c * DEMO_TOK + kg]
                                    : Vo[(long)c * OBS_TOK + (kg - DEMO_TOK)];
            KV[ii * 36 + c] = v;
        }
        __syncthreads();
        // AV (packed along channel pairs)
#pragma unroll 4
        for (int k = 0; k < 64; k++) {
            ulonglong2 v2 = *(const ulonglong2*)&KV[k * 36 + w * 4];
            const float* pr = &Ps[k * 200 + jg];
            unsigned long long pp0 = pk2(pr[0]);
            unsigned long long pp1 = pk2(pr[32]);
            unsigned long long pp2 = pk2(pr[64]);
            unsigned long long pp3 = pk2(pr[96]);
            unsigned long long pp4 = pk2(pr[128]);
            unsigned long long pp5 = pk2(pr[160]);
            unsigned long long pp6 = pk2(has7 ? pr[192] : 0.f);
            out2[0][0] = fma2(v2.x, pp0, out2[0][0]); out2[1][0] = fma2(v2.y, pp0, out2[1][0]);
            out2[0][1] = fma2(v2.x, pp1, out2[0][1]); out2[1][1] = fma2(v2.y, pp1, out2[1][1]);
            out2[0][2] = fma2(v2.x, pp2, out2[0][2]); out2[1][2] = fma2(v2.y, pp2, out2[1][2]);
            out2[0][3] = fma2(v2.x, pp3, out2[0][3]); out2[1][3] = fma2(v2.y, pp3, out2[1][3]);
            out2[0][4] = fma2(v2.x, pp4, out2[0][4]); out2[1][4] = fma2(v2.y, pp4, out2[1][4]);
            out2[0][5] = fma2(v2.x, pp5, out2[0][5]); out2[1][5] = fma2(v2.y, pp5, out2[1][5]);
            out2[0][6] = fma2(v2.x, pp6, out2[0][6]); out2[1][6] = fma2(v2.y, pp6, out2[1][6]);
        }
    }
    float* op = part + ((long)(khalf * 384 + z)) * 6272;
#pragma unroll
    for (int u = 0; u < 2; u++)
#pragma unroll
        for (int q = 0; q < 7; q++) {
            int j = jg + 32 * q;
            if (j < 196) {
                float2 f = upk(out2[u][q]);
                op[(w * 4 + u * 2 + 0) * 196 + j] = f.x;
                op[(w * 4 + u * 2 + 1) * 196 + j] = f.y;
            }
        }
}

// ---------------- merge obs AV partials into g_mg (conv layout) ----------------
__global__ void k_merge(const float* __restrict__ part) {
    int z = blockIdx.y;
    int e = blockIdx.x * 256 + threadIdx.x;
    if (e >= 6272) return;
    int c = e / 196, j = e - c * 196;
    int b = z / 96, tt = (z >> 3) % 12, h = z & 7;
    float v = part[(long)z * 6272 + e] + part[(long)(384 + z) * 6272 + e];
    g_mg[((long)b * 256 + h * 32 + c) * OBS_TOK + tt * 196 + j] = v;
}

// ---------------- BatchNorm stats ----------------
__global__ void k_bnstats() {
    const int c = blockIdx.x;
    float s = 0.f, s2 = 0.f;
    for (int e = threadIdx.x; e < BB * THW; e += 256) {
        int b = e / THW, k = e - b * THW;
        float v = g_x[(long)b * CTHW + (long)c * THW + k];
        s += v; s2 += v * v;
    }
#pragma unroll
    for (int o = 16; o; o >>= 1) {
        s  += __shfl_xor_sync(0xffffffffu, s, o);
        s2 += __shfl_xor_sync(0xffffffffu, s2, o);
    }
    __shared__ float ws[8], ws2[8];
    int w = threadIdx.x >> 5;
    if ((threadIdx.x & 31) == 0) { ws[w] = s; ws2[w] = s2; }
    __syncthreads();
    if (threadIdx.x == 0) {
        float S = 0.f, S2 = 0.f;
#pragma unroll
        for (int i = 0; i < 8; i++) { S += ws[i]; S2 += ws2[i]; }
        float m = S * (1.f / 12544.f);
        float var = S2 * (1.f / 12544.f) - m * m;
        g_mean[c] = m;
        g_istd[c] = rsqrtf(var + EPSV);
    }
}

// ---------------- BatchNorm apply ----------------
__global__ void k_bnapply(const float* __restrict__ gamma, const float* __restrict__ beta,
                          float* __restrict__ out) {
    int e = blockIdx.x * 256 + threadIdx.x;
    int c = (e / 784) & 255;
    float4 v = ((const float4*)g_x)[e];
    float a = gamma[c] * g_istd[c];
    float b2 = beta[c] - g_mean[c] * a;
    v.x = v.x * a + b2; v.y = v.y * a + b2; v.z = v.z * a + b2; v.w = v.w * a + b2;
    ((float4*)out)[e] = v;
}

// ---------------- host orchestration ----------------
extern "C" void kernel_launch(void* const* d_in, const int* in_sizes, int n_in,
                              void* d_out, int out_size) {
    const float* x    = (const float*)d_in[0];
    const float* w_dq = (const float*)d_in[1];
    const float* w_dk = (const float*)d_in[2];
    const float* w_dv = (const float*)d_in[3];
    const float* w_oq = (const float*)d_in[4];
    const float* w_ok = (const float*)d_in[5];
    const float* w_ov = (const float*)d_in[6];
    const float* w_oo = (const float*)d_in[7];
    const float* gam  = (const float*)d_in[8];
    const float* bet  = (const float*)d_in[9];
    float* out = (float*)d_out;

    float *p_x, *p_dq, *p_dk, *p_dv, *p_oq, *p_ok, *p_ov, *p_mg, *p_part;
    cudaGetSymbolAddress((void**)&p_x,  g_x);
    cudaGetSymbolAddress((void**)&p_dq, g_dq);
    cudaGetSymbolAddress((void**)&p_dk, g_dk);
    cudaGetSymbolAddress((void**)&p_dv, g_dv);
    cudaGetSymbolAddress((void**)&p_oq, g_oq);
    cudaGetSymbolAddress((void**)&p_ok, g_ok);
    cudaGetSymbolAddress((void**)&p_ov, g_ov);
    cudaGetSymbolAddress((void**)&p_mg, g_mg);
    cudaGetSymbolAddress((void**)&p_part, g_part);

    cudaFuncSetAttribute(k_obs_fused, cudaFuncAttributeMaxDynamicSharedMemorySize, 87040);

    k_copy<<<3136, 256>>>((const float4*)x);

    const long xbs = (long)CTHW;
    const long dbs = (long)256 * DEMO_TOK;
    const long obs = (long)256 * OBS_TOK;
    dim3 cg_demo(13, 12, BB), cg_obs(37, 12, BB), cg_out(37, 4, BB);

    for (int l = 0; l < 3; l++) {
        const int WO = l * 256 * 256;
        k_conv3<<<cg_demo, 256>>>(w_dq + WO, w_dk + WO, w_dv + WO,
                                  p_x, THW, 0, xbs,
                                  p_dq, p_dk, p_dv, DEMO_TOK, 0, dbs, DEMO_TOK, 0);
        k_conv3<<<cg_obs, 256>>>(w_oq + WO, w_ok + WO, w_ov + WO,
                                 p_x, THW, DEMO_TOK, xbs,
                                 p_oq, p_ok, p_ov, OBS_TOK, 0, obs, OBS_TOK, 0);
        k_demo_fused<<<dim3(49, 32), 256>>>();
        k_obs_fused<<<dim3(384, 2), 256, 87040>>>(p_part);
        k_merge<<<dim3(25, 384), 256>>>(p_part);
        k_conv3<<<cg_out, 256>>>(w_oo + WO, w_oo + WO, w_oo + WO,
                                 p_mg, OBS_TOK, 0, obs,
                                 p_x, p_x, p_x, THW, DEMO_TOK, xbs, OBS_TOK, 1);
        k_bnstats<<<256, 256>>>();
        k_bnapply<<<3136, 256>>>(gam + l * 256, bet + l * 256, (l == 2) ? out : p_x);
    }
}

// round 10
// speedup vs baseline: 2.0143x; 1.0587x over previous
#include <cuda_runtime.h>
#include <cstdint>

// ---------------- problem constants ----------------
#define BB 4
#define THW 3136          // 16*14*14
#define DEMO_TOK 784
#define OBS_TOK 2352
#define INV_TEMP 0.0625f  // 1/sqrt(256)
#define EPSV 1e-5f
#define CTHW (256*THW)    // 802816

// ---------------- scratch (device globals; allocation-free) ----------------
__device__ __align__(256) float g_x[BB*CTHW];
__device__ __align__(256) float g_dq[BB*256*DEMO_TOK];
__device__ __align__(256) float g_dk[BB*256*DEMO_TOK];
__device__ __align__(256) float g_dv[BB*256*DEMO_TOK];
__device__ __align__(256) float g_dvatt[BB*256*DEMO_TOK];
__device__ __align__(256) float g_oq[BB*256*OBS_TOK];
__device__ __align__(256) float g_ok[BB*256*OBS_TOK];
__device__ __align__(256) float g_ov[BB*256*OBS_TOK];
__device__ __align__(256) float g_mg[BB*256*OBS_TOK];
__device__ __align__(256) float g_part[2*384*32*196];   // obs AV partials (k-split)
__device__ float g_mean[256];
__device__ float g_istd[256];

// ---------------- packed f32x2 helpers ----------------
__device__ __forceinline__ unsigned long long pk2(float x) {
    unsigned long long r;
    asm("mov.b64 %0, {%1, %1};" : "=l"(r) : "f"(x));
    return r;
}
__device__ __forceinline__ unsigned long long fma2(
    unsigned long long a, unsigned long long b, unsigned long long c) {
    unsigned long long d;
    asm("fma.rn.f32x2 %0, %1, %2, %3;" : "=l"(d) : "l"(a), "l"(b), "l"(c));
    return d;
}
__device__ __forceinline__ float2 upk(unsigned long long v) {
    float2 f;
    asm("mov.b64 {%0, %1}, %2;" : "=f"(f.x), "=f"(f.y) : "l"(v));
    return f;
}

// ---------------- cp.async helpers ----------------
__device__ __forceinline__ void cp_async16(uint32_t dst, const void* src, int bytes) {
    asm volatile("cp.async.cg.shared.global [%0], [%1], 16, %2;\n"
                 :: "r"(dst), "l"(src), "r"(bytes));
}
__device__ __forceinline__ void cp_async4(uint32_t dst, const void* src, int srcsz) {
    asm volatile("cp.async.ca.shared.global [%0], [%1], 4, %2;\n"
                 :: "r"(dst), "l"(src), "r"(srcsz));
}
__device__ __forceinline__ void cp_commit() {
    asm volatile("cp.async.commit_group;\n");
}
template<int N> __device__ __forceinline__ void cp_wait() {
    asm volatile("cp.async.wait_group %0;\n" :: "n"(N));
}

// ---------------- copy input -> g_x ----------------
__global__ void k_copy(const float4* __restrict__ src) {
    int e = blockIdx.x * 256 + threadIdx.x;
    ((float4*)g_x)[e] = src[e];
}

// ---------------- fused triple 1x1-conv GEMM, cp.async + FFMA2 ----------------
__global__ __launch_bounds__(256) void k_conv3(
    const float* __restrict__ W0, const float* __restrict__ W1, const float* __restrict__ W2,
    const float* __restrict__ X, int ldx, int xoff, long xbstr,
    float* __restrict__ O0, float* __restrict__ O1, float* __restrict__ O2,
    int ldo, int ooff, long obstr, int N, int fuse)
{
    __shared__ float As[2][64*36];
    __shared__ float Bs[2][32*64];
    const int t  = threadIdx.x;
    const int b  = blockIdx.z;
    const int my = blockIdx.y;
    const int sel = my >> 2;
    const int m0  = (my & 3) * 64;
    const int n0  = blockIdx.x * 64;
    const float* W = (sel == 0) ? W0 : ((sel == 1) ? W1 : W2);
    float* Obase   = (sel == 0) ? O0 : ((sel == 1) ? O1 : O2);
    const float* Xb = X + b * xbstr + xoff;
    const int ty = t >> 4, tx = t & 15;

    const int am = t >> 3, aq = t & 7;
    const int bk = t >> 4, bn = t & 15;
    const int ncol = n0 + bn * 4;
    const int bbytes = (ncol + 4 <= N) ? 16 : 0;
    const float* asrc0 = &W[(m0 + am) * 256 + aq * 4];
    const float* asrc1 = asrc0 + 32 * 256;
    const float* bsrc  = Xb + (long)bk * ldx + (bbytes ? ncol : n0);
    uint32_t asb = (uint32_t)__cvta_generic_to_shared(&As[0][0]);
    uint32_t bsb = (uint32_t)__cvta_generic_to_shared(&Bs[0][0]);
    const uint32_t ad0 = asb + (uint32_t)((am * 36 + aq * 4) * 4);
    const uint32_t ad1 = asb + (uint32_t)(((am + 32) * 36 + aq * 4) * 4);
    const uint32_t bd0 = bsb + (uint32_t)((bk * 64 + bn * 4) * 4);
    const uint32_t bd1 = bsb + (uint32_t)(((bk + 16) * 64 + bn * 4) * 4);
    const uint32_t ABUF = 64 * 36 * 4, BBUF = 32 * 64 * 4;

#define PREF(K0, S) do { \
    cp_async16(ad0 + (S) * ABUF, asrc0 + (K0) * 32, 16); \
    cp_async16(ad1 + (S) * ABUF, asrc1 + (K0) * 32, 16); \
    cp_async16(bd0 + (S) * BBUF, bsrc + (long)((K0) * 32) * ldx, bbytes); \
    cp_async16(bd1 + (S) * BBUF, bsrc + (long)((K0) * 32 + 16) * ldx, bbytes); \
    cp_commit(); } while (0)

    unsigned long long acc2[4][2];
#pragma unroll
    for (int i = 0; i < 4; i++) { acc2[i][0] = 0ull; acc2[i][1] = 0ull; }

    PREF(0, 0);
    for (int k0 = 0; k0 < 8; k0++) {
        const int cur = k0 & 1;
        if (k0 < 7) { PREF(k0 + 1, cur ^ 1); cp_wait<1>(); }
        else        { cp_wait<0>(); }
        __syncthreads();
        const float* Ac = &As[cur][0];
        const float* Bc = &Bs[cur][0];
#pragma unroll
        for (int k4 = 0; k4 < 8; k4++) {
            float4 a4[4]; ulonglong2 b2[4];
#pragma unroll
            for (int i = 0; i < 4; i++)
                a4[i] = *(const float4*)&Ac[(ty * 4 + i) * 36 + k4 * 4];
#pragma unroll
            for (int kk = 0; kk < 4; kk++)
                b2[kk] = *(const ulonglong2*)&Bc[(k4 * 4 + kk) * 64 + tx * 4];
#pragma unroll
            for (int kk = 0; kk < 4; kk++) {
#pragma unroll
                for (int i = 0; i < 4; i++) {
                    float av = (kk == 0) ? a4[i].x : (kk == 1) ? a4[i].y
                             : (kk == 2) ? a4[i].z : a4[i].w;
                    unsigned long long aa = pk2(av);
                    acc2[i][0] = fma2(aa, b2[kk].x, acc2[i][0]);
                    acc2[i][1] = fma2(aa, b2[kk].y, acc2[i][1]);
                }
            }
        }
        __syncthreads();
    }
#undef PREF

    float* Ob = Obase + b * obstr + ooff;
#pragma unroll
    for (int i = 0; i < 4; i++) {
        int m = m0 + ty * 4 + i;
        float2 p0 = upk(acc2[i][0]), p1 = upk(acc2[i][1]);
        float accf[4] = {p0.x, p0.y, p1.x, p1.y};
#pragma unroll
        for (int j = 0; j < 4; j++) {
            int n = n0 + tx * 4 + j;
            if (n < N) {
                float* p = Ob + (long)m * ldo + n;
                if (fuse) *p = *p + fmaxf(accf[j], 0.f);
                else      *p = accf[j];
            }
        }
    }
}

// ---------------- fused demo attention: scores + softmax + AV (FFMA2) ----------------
__global__ __launch_bounds__(256, 2) void k_demo_fused() {
    const int t = threadIdx.x;
    const int itile = blockIdx.x;        // 0..48
    const int bh = blockIdx.y;           // 0..31
    const int b = bh >> 3, h = bh & 7;
    const float* Kp = g_dk + ((long)b * 256 + h * 32) * DEMO_TOK;
    const float* Qp = g_dq + ((long)b * 256 + h * 32) * DEMO_TOK;
    const float* Vp = g_dv + ((long)b * 256 + h * 32) * DEMO_TOK;
    __shared__ float Ks[512];
    __shared__ float Red[256];
    __shared__ float Big[7488];
    const int r = t & 15;
    const int g = t >> 4;
    const int wc = t >> 5;
    const int ln = t & 31;
    unsigned long long acc2[24];
    float acc48 = 0.f;
#pragma unroll
    for (int p = 0; p < 24; p++) acc2[p] = 0ull;

#pragma unroll
    for (int e = t; e < 512; e += 256) {
        int c = e >> 4, ii = e & 15;
        Ks[c * 16 + ii] = Kp[(long)c * DEMO_TOK + itile * 16 + ii];
    }
    for (int cb = 0; cb < 4; cb++) {
        __syncthreads();
        {
            const float* qsrc = Qp + (long)(cb * 8 + wc) * DEMO_TOK;
            float* qdst = &Big[wc * 832];
#pragma unroll
            for (int jq = 0; jq < 16; jq++) {
#pragma unroll
                for (int half = 0; half < 2; half++) {
                    int jr = ln + half * 32;
                    if (jr < 49)
                        qdst[jq * 52 + jr] = qsrc[jq * 49 + jr];
                }
            }
        }
        __syncthreads();
#pragma unroll
        for (int cc = 0; cc < 8; cc++) {
            float a = Ks[(cb * 8 + cc) * 16 + r];
            unsigned long long aa = pk2(a);
            const ulonglong2* q2 = (const ulonglong2*)&Big[cc * 832 + g * 52];
#pragma unroll
            for (int v = 0; v < 12; v++) {
                ulonglong2 qq = q2[v];
                acc2[v*2+0] = fma2(aa, qq.x, acc2[v*2+0]);
                acc2[v*2+1] = fma2(aa, qq.y, acc2[v*2+1]);
            }
            acc48 += a * Big[cc * 832 + g * 52 + 48];
        }
    }
    float acc[49];
#pragma unroll
    for (int p = 0; p < 24; p++) {
        float2 f = upk(acc2[p]);
        acc[p*2] = f.x; acc[p*2+1] = f.y;
    }
    acc[48] = acc48;
    float mx = -1e30f;
#pragma unroll
    for (int jj = 0; jj < 49; jj++) { acc[jj] *= INV_TEMP; mx = fmaxf(mx, acc[jj]); }
    __syncthreads();
    Red[g * 16 + r] = mx;
    __syncthreads();
    float gm = Red[r];
#pragma unroll
    for (int gg = 1; gg < 16; gg++) gm = fmaxf(gm, Red[gg * 16 + r]);
    __syncthreads();
    float sm = 0.f;
#pragma unroll
    for (int jj = 0; jj < 49; jj++) { float p = __expf(acc[jj] - gm); acc[jj] = p; sm += p; }
    Red[g * 16 + r] = sm;
    __syncthreads();
    float gs = Red[r];
#pragma unroll
    for (int gg = 1; gg < 16; gg++) gs += Red[gg * 16 + r];
    float inv = 1.f / gs;
#pragma unroll
    for (int jj = 0; jj < 49; jj++) acc[jj] *= inv;

    unsigned long long pacc2[16];
#pragma unroll
    for (int p = 0; p < 16; p++) pacc2[p] = 0ull;
#pragma unroll
    for (int tile = 0; tile < 4; tile++) {
        __syncthreads();
        {
            const int ndj = (tile < 3) ? 13 : 10;
            if (ln < ndj) {
#pragma unroll 16
                for (int it = 0; it < 64; it++) {
                    int c  = wc * 4 + (it >> 4);
                    int gg = it & 15;
                    Big[(gg * 13 + ln) * 36 + c] =
                        Vp[(long)c * DEMO_TOK + gg * 49 + tile * 13 + ln];
                }
            }
        }
        __syncthreads();
#pragma unroll
        for (int dj = 0; dj < 13; dj++) {
            const int jj = tile * 13 + dj;
            if (jj >= 49) break;
            unsigned long long pp = pk2(acc[jj]);
            const ulonglong2* vb2 = (const ulonglong2*)&Big[(g * 13 + dj) * 36];
#pragma unroll
            for (int u = 0; u < 8; u++) {
                ulonglong2 v = vb2[u];
                pacc2[u*2+0] = fma2(v.x, pp, pacc2[u*2+0]);
                pacc2[u*2+1] = fma2(v.y, pp, pacc2[u*2+1]);
            }
        }
    }
    float pacc[32];
#pragma unroll
    for (int p = 0; p < 16; p++) {
        float2 f = upk(pacc2[p]);
        pacc[p*2] = f.x; pacc[p*2+1] = f.y;
    }
#pragma unroll
    for (int ch = 0; ch < 2; ch++) {
        __syncthreads();
#pragma unroll
        for (int cc = 0; cc < 16; cc++)
            Big[t * 17 + cc] = pacc[ch * 16 + cc];
        __syncthreads();
        int rr = t >> 4, cc = t & 15;
        float s = 0.f;
#pragma unroll
        for (int gg = 0; gg < 16; gg++)
            s += Big[(gg * 16 + rr) * 17 + cc];
        g_dvatt[((long)b * 256 + h * 32 + ch * 16 + cc) * DEMO_TOK + itile * 16 + rr] = s;
    }
}

// ---------------- fused obs attention: cp.async double-buffered K/V pipeline ----------------
// smem: Ps[64][200] | Qs[32][208] | Kb[2][32*64] | Vb[2][64*36]  = 28160 floats = 112640 B
__global__ __launch_bounds__(256, 2) void k_obs_fused(float* __restrict__ part) {
    extern __shared__ float smem[];
    float* Ps = smem;              // [64][200]
    float* Qs = smem + 12800;      // [32][208]
    float* Kb = smem + 19456;      // [2][2048]
    float* Vb = smem + 23552;      // [2][2304]
    const int z = blockIdx.x;
    const int khalf = blockIdx.y;
    const int b = z / 96, tt = (z >> 3) % 12, h = z & 7;
    const int t = threadIdx.x;
    const float* Kd = g_dk    + ((long)b * 256 + h * 32) * DEMO_TOK;
    const float* Ko = g_ok    + ((long)b * 256 + h * 32) * OBS_TOK + tt * 196;
    const float* Vd = g_dvatt + ((long)b * 256 + h * 32) * DEMO_TOK;
    const float* Vo = g_ov    + ((long)b * 256 + h * 32) * OBS_TOK + tt * 196;
    const float* Qp = g_oq    + ((long)b * 256 + h * 32) * OBS_TOK + tt * 196;
    const uint32_t kbs = (uint32_t)__cvta_generic_to_shared(Kb);
    const uint32_t vbs = (uint32_t)__cvta_generic_to_shared(Vb);
    const int kbase = khalf * 490;

    // Q resident for the whole block
    for (int e = t; e < 6272; e += 256) {
        int c = e / 196, j = e - c * 196;
        Qs[c * 208 + (j / 49) * 52 + (j % 49)] = Qp[(long)c * OBS_TOK + j];
    }

#define PREF_K(KT, S) do { \
    _Pragma("unroll") \
    for (int i_ = 0; i_ < 8; i_++) { \
        int e_ = i_ * 256 + t; \
        int c_ = e_ >> 6, ii_ = e_ & 63; \
        int kl_ = (KT) * 64 + ii_; \
        int sz_ = (kl_ < 490) ? 4 : 0; \
        int kg_ = kbase + ((kl_ < 490) ? kl_ : 0); \
        const float* s_ = (kg_ < DEMO_TOK) ? (Kd + (long)c_ * DEMO_TOK + kg_) \
                                           : (Ko + (long)c_ * OBS_TOK + (kg_ - DEMO_TOK)); \
        cp_async4(kbs + (uint32_t)(((S) * 2048 + c_ * 64 + ii_) * 4), s_, sz_); \
    } cp_commit(); } while (0)

#define PREF_V(KT, S) do { \
    _Pragma("unroll") \
    for (int i_ = 0; i_ < 8; i_++) { \
        int e_ = i_ * 256 + t; \
        int c_ = e_ >> 6, ii_ = e_ & 63; \
        int kl_ = (KT) * 64 + ii_; \
        int sz_ = (kl_ < 490) ? 4 : 0; \
        int kg_ = kbase + ((kl_ < 490) ? kl_ : 0); \
        const float* s_ = (kg_ < DEMO_TOK) ? (Vd + (long)c_ * DEMO_TOK + kg_) \
                                           : (Vo + (long)c_ * OBS_TOK + (kg_ - DEMO_TOK)); \
        cp_async4(vbs + (uint32_t)(((S) * 2304 + ii_ * 36 + c_) * 4), s_, sz_); \
    } cp_commit(); } while (0)

    const int r = t >> 2, gq = t & 3;
    const int w = t >> 5, jg = t & 31;
    const bool has7 = (jg < 4);
    unsigned long long out2[2][7];
#pragma unroll
    for (int cc = 0; cc < 2; cc++)
#pragma unroll
        for (int q = 0; q < 7; q++) out2[cc][q] = 0ull;

    PREF_K(0, 0);
    PREF_V(0, 0);

    for (int kt = 0; kt < 8; kt++) {
        const int cur = kt & 1;
        if (kt < 7) { PREF_K(kt + 1, cur ^ 1); cp_wait<2>(); }
        else        { cp_wait<1>(); }
        __syncthreads();
        const float* Kc = Kb + cur * 2048;
        // scores (packed)
        unsigned long long acc2[24];
        float acc48 = 0.f;
#pragma unroll
        for (int p = 0; p < 24; p++) acc2[p] = 0ull;
#pragma unroll
        for (int c = 0; c < 32; c++) {
            float a = Kc[c * 64 + r];
            unsigned long long aa = pk2(a);
            const ulonglong2* q2 = (const ulonglong2*)&Qs[c * 208 + gq * 52];
#pragma unroll
            for (int v = 0; v < 12; v++) {
                ulonglong2 qq = q2[v];
                acc2[v*2+0] = fma2(aa, qq.x, acc2[v*2+0]);
                acc2[v*2+1] = fma2(aa, qq.y, acc2[v*2+1]);
            }
            acc48 += a * Qs[c * 208 + gq * 52 + 48];
        }
        float acc[49];
#pragma unroll
        for (int p = 0; p < 24; p++) {
            float2 f = upk(acc2[p]);
            acc[p*2] = f.x; acc[p*2+1] = f.y;
        }
        acc[48] = acc48;
        float mx = -1e30f;
#pragma unroll
        for (int jj = 0; jj < 49; jj++) { acc[jj] *= INV_TEMP; mx = fmaxf(mx, acc[jj]); }
        mx = fmaxf(mx, __shfl_xor_sync(0xffffffffu, mx, 1));
        mx = fmaxf(mx, __shfl_xor_sync(0xffffffffu, mx, 2));
        float sm = 0.f;
#pragma unroll
        for (int jj = 0; jj < 49; jj++) { float p = __expf(acc[jj] - mx); acc[jj] = p; sm += p; }
        sm += __shfl_xor_sync(0xffffffffu, sm, 1);
        sm += __shfl_xor_sync(0xffffffffu, sm, 2);
        float inv = 1.f / sm;
        {
            float* pr = &Ps[r * 200 + gq * 49];
#pragma unroll
            for (int jj = 0; jj < 49; jj++) pr[jj] = acc[jj] * inv;
        }
        if (kt < 7) { PREF_V(kt + 1, cur ^ 1); cp_wait<2>(); }
        else        { cp_wait<0>(); }
        __syncthreads();
        const float* Vc = Vb + cur * 2304;
        // AV (packed along channel pairs)
#pragma unroll 4
        for (int k = 0; k < 64; k++) {
            ulonglong2 v2 = *(const ulonglong2*)&Vc[k * 36 + w * 4];
            const float* pr = &Ps[k * 200 + jg];
            unsigned long long pp0 = pk2(pr[0]);
            unsigned long long pp1 = pk2(pr[32]);
            unsigned long long pp2 = pk2(pr[64]);
            unsigned long long pp3 = pk2(pr[96]);
            unsigned long long pp4 = pk2(pr[128]);
            unsigned long long pp5 = pk2(pr[160]);
            unsigned long long pp6 = pk2(has7 ? pr[192] : 0.f);
            out2[0][0] = fma2(v2.x, pp0, out2[0][0]); out2[1][0] = fma2(v2.y, pp0, out2[1][0]);
            out2[0][1] = fma2(v2.x, pp1, out2[0][1]); out2[1][1] = fma2(v2.y, pp1, out2[1][1]);
            out2[0][2] = fma2(v2.x, pp2, out2[0][2]); out2[1][2] = fma2(v2.y, pp2, out2[1][2]);
            out2[0][3] = fma2(v2.x, pp3, out2[0][3]); out2[1][3] = fma2(v2.y, pp3, out2[1][3]);
            out2[0][4] = fma2(v2.x, pp4, out2[0][4]); out2[1][4] = fma2(v2.y, pp4, out2[1][4]);
            out2[0][5] = fma2(v2.x, pp5, out2[0][5]); out2[1][5] = fma2(v2.y, pp5, out2[1][5]);
            out2[0][6] = fma2(v2.x, pp6, out2[0][6]); out2[1][6] = fma2(v2.y, pp6, out2[1][6]);
        }
    }
#undef PREF_K
#undef PREF_V
    float* op = part + ((long)(khalf * 384 + z)) * 6272;
#pragma unroll
    for (int u = 0; u < 2; u++)
#pragma unroll
        for (int q = 0; q < 7; q++) {
            int j = jg + 32 * q;
            if (j < 196) {
                float2 f = upk(out2[u][q]);
                op[(w * 4 + u * 2 + 0) * 196 + j] = f.x;
                op[(w * 4 + u * 2 + 1) * 196 + j] = f.y;
            }
        }
}

// ---------------- merge obs AV partials into g_mg (conv layout) ----------------
__global__ void k_merge(const float* __restrict__ part) {
    int z = blockIdx.y;
    int e = blockIdx.x * 256 + threadIdx.x;
    if (e >= 6272) return;
    int c = e / 196, j = e - c * 196;
    int b = z / 96, tt = (z >> 3) % 12, h = z & 7;
    float v = part[(long)z * 6272 + e] + part[(long)(384 + z) * 6272 + e];
    g_mg[((long)b * 256 + h * 32 + c) * OBS_TOK + tt * 196 + j] = v;
}

// ---------------- BatchNorm stats ----------------
__global__ void k_bnstats() {
    const int c = blockIdx.x;
    float s = 0.f, s2 = 0.f;
    for (int e = threadIdx.x; e < BB * THW; e += 256) {
        int b = e / THW, k = e - b * THW;
        float v = g_x[(long)b * CTHW + (long)c * THW + k];
        s += v; s2 += v * v;
    }
#pragma unroll
    for (int o = 16; o; o >>= 1) {
        s  += __shfl_xor_sync(0xffffffffu, s, o);
        s2 += __shfl_xor_sync(0xffffffffu, s2, o);
    }
    __shared__ float ws[8], ws2[8];
    int w = threadIdx.x >> 5;
    if ((threadIdx.x & 31) == 0) { ws[w] = s; ws2[w] = s2; }
    __syncthreads();
    if (threadIdx.x == 0) {
        float S = 0.f, S2 = 0.f;
#pragma unroll
        for (int i = 0; i < 8; i++) { S += ws[i]; S2 += ws2[i]; }
        float m = S * (1.f / 12544.f);
        float var = S2 * (1.f / 12544.f) - m * m;
        g_mean[c] = m;
        g_istd[c] = rsqrtf(var + EPSV);
    }
}

// ---------------- BatchNorm apply ----------------
__global__ void k_bnapply(const float* __restrict__ gamma, const float* __restrict__ beta,
                          float* __restrict__ out) {
    int e = blockIdx.x * 256 + threadIdx.x;
    int c = (e / 784) & 255;
    float4 v = ((const float4*)g_x)[e];
    float a = gamma[c] * g_istd[c];
    float b2 = beta[c] - g_mean[c] * a;
    v.x = v.x * a + b2; v.y = v.y * a + b2; v.z = v.z * a + b2; v.w = v.w * a + b2;
    ((float4*)out)[e] = v;
}

// ---------------- host orchestration ----------------
extern "C" void kernel_launch(void* const* d_in, const int* in_sizes, int n_in,
                              void* d_out, int out_size) {
    const float* x    = (const float*)d_in[0];
    const float* w_dq = (const float*)d_in[1];
    const float* w_dk = (const float*)d_in[2];
    const float* w_dv = (const float*)d_in[3];
    const float* w_oq = (const float*)d_in[4];
    const float* w_ok = (const float*)d_in[5];
    const float* w_ov = (const float*)d_in[6];
    const float* w_oo = (const float*)d_in[7];
    const float* gam  = (const float*)d_in[8];
    const float* bet  = (const float*)d_in[9];
    float* out = (float*)d_out;

    float *p_x, *p_dq, *p_dk, *p_dv, *p_oq, *p_ok, *p_ov, *p_mg, *p_part;
    cudaGetSymbolAddress((void**)&p_x,  g_x);
    cudaGetSymbolAddress((void**)&p_dq, g_dq);
    cudaGetSymbolAddress((void**)&p_dk, g_dk);
    cudaGetSymbolAddress((void**)&p_dv, g_dv);
    cudaGetSymbolAddress((void**)&p_oq, g_oq);
    cudaGetSymbolAddress((void**)&p_ok, g_ok);
    cudaGetSymbolAddress((void**)&p_ov, g_ov);
    cudaGetSymbolAddress((void**)&p_mg, g_mg);
    cudaGetSymbolAddress((void**)&p_part, g_part);

    cudaFuncSetAttribute(k_obs_fused, cudaFuncAttributeMaxDynamicSharedMemorySize, 112640);

    k_copy<<<3136, 256>>>((const float4*)x);

    const long xbs = (long)CTHW;
    const long dbs = (long)256 * DEMO_TOK;
    const long obs = (long)256 * OBS_TOK;
    dim3 cg_demo(13, 12, BB), cg_obs(37, 12, BB), cg_out(37, 4, BB);

    for (int l = 0; l < 3; l++) {
        const int WO = l * 256 * 256;
        k_conv3<<<cg_demo, 256>>>(w_dq + WO, w_dk + WO, w_dv + WO,
                                  p_x, THW, 0, xbs,
                                  p_dq, p_dk, p_dv, DEMO_TOK, 0, dbs, DEMO_TOK, 0);
        k_conv3<<<cg_obs, 256>>>(w_oq + WO, w_ok + WO, w_ov + WO,
                                 p_x, THW, DEMO_TOK, xbs,
                                 p_oq, p_ok, p_ov, OBS_TOK, 0, obs, OBS_TOK, 0);
        k_demo_fused<<<dim3(49, 32), 256>>>();
        k_obs_fused<<<dim3(384, 2), 256, 112640>>>(p_part);
        k_merge<<<dim3(25, 384), 256>>>(p_part);
        k_conv3<<<cg_out, 256>>>(w_oo + WO, w_oo + WO, w_oo + WO,
                                 p_mg, OBS_TOK, 0, obs,
                                 p_x, p_x, p_x, THW, DEMO_TOK, xbs, OBS_TOK, 1);
        k_bnstats<<<256, 256>>>();
        k_bnapply<<<3136, 256>>>(gam + l * 256, bet + l * 256, (l == 2) ? out : p_x);
    }
}

// round 12
// speedup vs baseline: 2.0181x; 1.0019x over previous
#include <cuda_runtime.h>
#include <cstdint>

#define BB 4
#define THW 3136
#define DEMO_TOK 784
#define OBS_TOK 2352
#define INV_TEMP 0.0625f
#define EPSV 1e-5f
#define CTHW (256*THW)

__device__ __align__(256) float g_x[BB*CTHW];
__device__ __align__(256) float g_dq[BB*256*DEMO_TOK];
__device__ __align__(256) float g_dk[BB*256*DEMO_TOK];
__device__ __align__(256) float g_dv[BB*256*DEMO_TOK];
__device__ __align__(256) float g_dvatt[BB*256*DEMO_TOK];
__device__ __align__(256) float g_oq[BB*256*OBS_TOK];
__device__ __align__(256) float g_ok[BB*256*OBS_TOK];
__device__ __align__(256) float g_ov[BB*256*OBS_TOK];
__device__ __align__(256) float g_mg[BB*256*OBS_TOK];
__device__ __align__(256) float g_part[2*384*32*196];
__device__ float g_mean[256];
__device__ float g_istd[256];

__device__ __forceinline__ unsigned long long pk2(float x) {
    unsigned long long r;
    asm("mov.b64 %0, {%1, %1};" : "=l"(r) : "f"(x));
    return r;
}
__device__ __forceinline__ unsigned long long fma2(
    unsigned long long a, unsigned long long b, unsigned long long c) {
    unsigned long long d;
    asm("fma.rn.f32x2 %0, %1, %2, %3;" : "=l"(d) : "l"(a), "l"(b), "l"(c));
    return d;
}
__device__ __forceinline__ float2 upk(unsigned long long v) {
    float2 f;
    asm("mov.b64 {%0, %1}, %2;" : "=f"(f.x), "=f"(f.y) : "l"(v));
    return f;
}

__device__ __forceinline__ void cp_async16(uint32_t dst, const void* src, int bytes) {
    asm volatile("cp.async.cg.shared.global [%0], [%1], 16, %2;\n"
                 :: "r"(dst), "l"(src), "r"(bytes));
}
__device__ __forceinline__ void cp_async4(uint32_t dst, const void* src, int srcsz) {
    asm volatile("cp.async.ca.shared.global [%0], [%1], 4, %2;\n"
                 :: "r"(dst), "l"(src), "r"(srcsz));
}
__device__ __forceinline__ void cp_commit() {
    asm volatile("cp.async.commit_group;\n");
}
template<int N> __device__ __forceinline__ void cp_wait() {
    asm volatile("cp.async.wait_group %0;\n" :: "n"(N));
}

__global__ void k_copy(const float4* __restrict__ src) {
    int e = blockIdx.x * 256 + threadIdx.x;
    ((float4*)g_x)[e] = src[e];
}

// ---------------- shared conv GEMM body (cp.async double-buffered, FFMA2) ----------------
__device__ __forceinline__ void conv_gemm(
    const float* __restrict__ W, const float* __restrict__ Xb,
    float* __restrict__ Ob, int ldx, int ldo, int N, int m0, int n0,
    int fuse, float* As, float* Bs, int t)
{
    const int ty = t >> 4, tx = t & 15;
    const int am = t >> 3, aq = t & 7;
    const int bk = t >> 4, bn = t & 15;
    const int ncol = n0 + bn * 4;
    const int bbytes = (ncol + 4 <= N) ? 16 : 0;
    const float* asrc0 = &W[(m0 + am) * 256 + aq * 4];
    const float* asrc1 = asrc0 + 32 * 256;
    const float* bsrc  = Xb + (long)bk * ldx + (bbytes ? ncol : n0);
    uint32_t asb = (uint32_t)__cvta_generic_to_shared(As);
    uint32_t bsb = (uint32_t)__cvta_generic_to_shared(Bs);
    const uint32_t ad0 = asb + (uint32_t)((am * 36 + aq * 4) * 4);
    const uint32_t ad1 = asb + (uint32_t)(((am + 32) * 36 + aq * 4) * 4);
    const uint32_t bd0 = bsb + (uint32_t)((bk * 64 + bn * 4) * 4);
    const uint32_t bd1 = bsb + (uint32_t)(((bk + 16) * 64 + bn * 4) * 4);
    const uint32_t ABUF = 64 * 36 * 4, BBUF = 32 * 64 * 4;

#define CPREF(K0, S) do { \
    cp_async16(ad0 + (S) * ABUF, asrc0 + (K0) * 32, 16); \
    cp_async16(ad1 + (S) * ABUF, asrc1 + (K0) * 32, 16); \
    cp_async16(bd0 + (S) * BBUF, bsrc + (long)((K0) * 32) * ldx, bbytes); \
    cp_async16(bd1 + (S) * BBUF, bsrc + (long)((K0) * 32 + 16) * ldx, bbytes); \
    cp_commit(); } while (0)

    unsigned long long acc2[4][2];
#pragma unroll
    for (int i = 0; i < 4; i++) { acc2[i][0] = 0ull; acc2[i][1] = 0ull; }

    CPREF(0, 0);
    for (int k0 = 0; k0 < 8; k0++) {
        const int cur = k0 & 1;
        if (k0 < 7) { CPREF(k0 + 1, cur ^ 1); cp_wait<1>(); }
        else        { cp_wait<0>(); }
        __syncthreads();
        const float* Ac = As + cur * (64 * 36);
        const float* Bc = Bs + cur * (32 * 64);
#pragma unroll
        for (int k4 = 0; k4 < 8; k4++) {
            float4 a4[4]; ulonglong2 b2[4];
#pragma unroll
            for (int i = 0; i < 4; i++)
                a4[i] = *(const float4*)&Ac[(ty * 4 + i) * 36 + k4 * 4];
#pragma unroll
            for (int kk = 0; kk < 4; kk++)
                b2[kk] = *(const ulonglong2*)&Bc[(k4 * 4 + kk) * 64 + tx * 4];
#pragma unroll
            for (int kk = 0; kk < 4; kk++) {
#pragma unroll
                for (int i = 0; i < 4; i++) {
                    float av = (kk == 0) ? a4[i].x : (kk == 1) ? a4[i].y
                             : (kk == 2) ? a4[i].z : a4[i].w;
                    unsigned long long aa = pk2(av);
                    acc2[i][0] = fma2(aa, b2[kk].x, acc2[i][0]);
                    acc2[i][1] = fma2(aa, b2[kk].y, acc2[i][1]);
                }
            }
        }
        __syncthreads();
    }
#undef CPREF

#pragma unroll
    for (int i = 0; i < 4; i++) {
        int m = m0 + ty * 4 + i;
        float2 p0 = upk(acc2[i][0]), p1 = upk(acc2[i][1]);
        float accf[4] = {p0.x, p0.y, p1.x, p1.y};
#pragma unroll
        for (int j = 0; j < 4; j++) {
            int n = n0 + tx * 4 + j;
            if (n < N) {
                float* p = Ob + (long)m * ldo + n;
                if (fuse) *p = *p + fmaxf(accf[j], 0.f);
                else      *p = accf[j];
            }
        }
    }
}

// ---------------- demo QKV conv ----------------
__global__ __launch_bounds__(256) void k_convD(
    const float* __restrict__ Wq, const float* __restrict__ Wk, const float* __restrict__ Wv)
{
    __shared__ float As[2][64*36];
    __shared__ float Bs[2][32*64];
    const int t = threadIdx.x, b = blockIdx.z, my = blockIdx.y;
    const int sel = my >> 2, m0 = (my & 3) * 64;
    const float* W = (sel == 0) ? Wq : ((sel == 1) ? Wk : Wv);
    const float* Xb = g_x + (long)b * CTHW;
    float* Ob = ((sel == 0) ? g_dq : (sel == 1) ? g_dk : g_dv) + (long)b * 256 * DEMO_TOK;
    conv_gemm(W, Xb, Ob, THW, DEMO_TOK, DEMO_TOK, m0, blockIdx.x * 64, 0,
              &As[0][0], &Bs[0][0], t);
}

// ---------------- obs QKV conv ----------------
__global__ __launch_bounds__(256) void k_convB(
    const float* __restrict__ Wq, const float* __restrict__ Wk, const float* __restrict__ Wv)
{
    __shared__ float As[2][64*36];
    __shared__ float Bs[2][32*64];
    const int t = threadIdx.x, b = blockIdx.z, my = blockIdx.y;
    const int sel = my >> 2, m0 = (my & 3) * 64;
    const float* W = (sel == 0) ? Wq : ((sel == 1) ? Wk : Wv);
    const float* Xb = g_x + (long)b * CTHW + DEMO_TOK;
    float* Ob = ((sel == 0) ? g_oq : (sel == 1) ? g_ok : g_ov) + (long)b * 256 * OBS_TOK;
    conv_gemm(W, Xb, Ob, THW, OBS_TOK, OBS_TOK, m0, blockIdx.x * 64, 0,
              &As[0][0], &Bs[0][0], t);
}

// ---------------- output conv (fused relu+residual) ----------------
__global__ __launch_bounds__(256) void k_convO(const float* __restrict__ Wo)
{
    __shared__ float As[2][64*36];
    __shared__ float Bs[2][32*64];
    const int t = threadIdx.x, b = blockIdx.z;
    const float* Xb = g_mg + (long)b * 256 * OBS_TOK;
    float* Ob = g_x + (long)b * CTHW + DEMO_TOK;
    conv_gemm(Wo, Xb, Ob, OBS_TOK, THW, OBS_TOK, blockIdx.y * 64, blockIdx.x * 64, 1,
              &As[0][0], &Bs[0][0], t);
}

// ---------------- fused demo attention: cp.async double-buffered Q/V ----------------
__global__ __launch_bounds__(256, 2) void k_demo_fused() {
    extern __shared__ float dyn[];       // 2 slots x 7488 floats
    __shared__ float Ks[512];
    __shared__ float Red[256];
    const int t = threadIdx.x;
    const int itile = blockIdx.x;
    const int bh = blockIdx.y;
    const int b = bh >> 3, h = bh & 7;
    const float* Kp = g_dk + ((long)b * 256 + h * 32) * DEMO_TOK;
    const float* Qp = g_dq + ((long)b * 256 + h * 32) * DEMO_TOK;
    const float* Vp = g_dv + ((long)b * 256 + h * 32) * DEMO_TOK;
    const uint32_t dsb = (uint32_t)__cvta_generic_to_shared(dyn);
    const int r = t & 15;
    const int g = t >> 4;
    const int wc = t >> 5;
    const int ln = t & 31;

#define PREF_Q(CB, S) do { \
    const float* qs_ = Qp + (long)((CB) * 8 + wc) * DEMO_TOK; \
    uint32_t qd_ = dsb + (uint32_t)(((S) * 7488 + wc * 832) * 4); \
    _Pragma("unroll") \
    for (int jq_ = 0; jq_ < 16; jq_++) { \
        _Pragma("unroll") \
        for (int hf_ = 0; hf_ < 2; hf_++) { \
            int jr_ = ln + hf_ * 32; \
            if (jr_ < 49) \
                cp_async4(qd_ + (uint32_t)((jq_ * 52 + jr_) * 4), qs_ + jq_ * 49 + jr_, 4); \
        } \
    } cp_commit(); } while (0)

#define PREF_V(TILE, S) do { \
    int jl_ = (TILE) * 13 + ln; \
    if (ln < 13 && jl_ < 49) { \
        _Pragma("unroll 16") \
        for (int it_ = 0; it_ < 64; it_++) { \
            int c_ = wc * 4 + (it_ >> 4); \
            int gg_ = it_ & 15; \
            cp_async4(dsb + (uint32_t)((((S) * 7488) + (gg_ * 13 + ln) * 36 + c_) * 4), \
                      Vp + (long)c_ * DEMO_TOK + gg_ * 49 + jl_, 4); \
        } \
    } cp_commit(); } while (0)

    unsigned long long acc2[24];
    float acc48 = 0.f;
#pragma unroll
    for (int p = 0; p < 24; p++) acc2[p] = 0ull;

#pragma unroll
    for (int e = t; e < 512; e += 256) {
        int c = e >> 4, ii = e & 15;
        Ks[c * 16 + ii] = Kp[(long)c * DEMO_TOK + itile * 16 + ii];
    }
    PREF_Q(0, 0);
    for (int cb = 0; cb < 4; cb++) {
        const int cur = cb & 1;
        if (cb < 3) PREF_Q(cb + 1, cur ^ 1);
        else        PREF_V(0, 0);
        cp_wait<1>();
        __syncthreads();
        const float* BigQ = dyn + cur * 7488;
#pragma unroll
        for (int cc = 0; cc < 8; cc++) {
            float a = Ks[(cb * 8 + cc) * 16 + r];
            unsigned long long aa = pk2(a);
            const ulonglong2* q2 = (const ulonglong2*)&BigQ[cc * 832 + g * 52];
#pragma unroll
            for (int v = 0; v < 12; v++) {
                ulonglong2 qq = q2[v];
                acc2[v*2+0] = fma2(aa, qq.x, acc2[v*2+0]);
                acc2[v*2+1] = fma2(aa, qq.y, acc2[v*2+1]);
            }
            acc48 += a * BigQ[cc * 832 + g * 52 + 48];
        }
        __syncthreads();
    }
    float acc[49];
#pragma unroll
    for (int p = 0; p < 24; p++) {
        float2 f = upk(acc2[p]);
        acc[p*2] = f.x; acc[p*2+1] = f.y;
    }
    acc[48] = acc48;
    float mx = -1e30f;
#pragma unroll
    for (int jj = 0; jj < 49; jj++) { acc[jj] *= INV_TEMP; mx = fmaxf(mx, acc[jj]); }
    Red[g * 16 + r] = mx;
    __syncthreads();
    float gm = Red[r];
#pragma unroll
    for (int gg = 1; gg < 16; gg++) gm = fmaxf(gm, Red[gg * 16 + r]);
    __syncthreads();
    float sm = 0.f;
#pragma unroll
    for (int jj = 0; jj < 49; jj++) { float p = __expf(acc[jj] - gm); acc[jj] = p; sm += p; }
    Red[g * 16 + r] = sm;
    __syncthreads();
    float gs = Red[r];
#pragma unroll
    for (int gg = 1; gg < 16; gg++) gs += Red[gg * 16 + r];
    float inv = 1.f / gs;
#pragma unroll
    for (int jj = 0; jj < 49; jj++) acc[jj] *= inv;

    unsigned long long pacc2[16];
#pragma unroll
    for (int p = 0; p < 16; p++) pacc2[p] = 0ull;
#pragma unroll
    for (int tile = 0; tile < 4; tile++) {
        const int vs = tile & 1;
        if (tile < 3) { PREF_V(tile + 1, vs ^ 1); cp_wait<1>(); }
        else          { cp_wait<0>(); }
        __syncthreads();
        const float* Vt = dyn + vs * 7488;
#pragma unroll
        for (int dj = 0; dj < 13; dj++) {
            const int jj = tile * 13 + dj;
            if (jj >= 49) break;
            unsigned long long pp = pk2(acc[jj]);
            const ulonglong2* vb2 = (const ulonglong2*)&Vt[(g * 13 + dj) * 36];
#pragma unroll
            for (int u = 0; u < 8; u++) {
                ulonglong2 v = vb2[u];
                pacc2[u*2+0] = fma2(v.x, pp, pacc2[u*2+0]);
                pacc2[u*2+1] = fma2(v.y, pp, pacc2[u*2+1]);
            }
        }
        __syncthreads();
    }
#undef PREF_Q
#undef PREF_V
    float pacc[32];
#pragma unroll
    for (int p = 0; p < 16; p++) {
        float2 f = upk(pacc2[p]);
        pacc[p*2] = f.x; pacc[p*2+1] = f.y;
    }
#pragma unroll
    for (int ch = 0; ch < 2; ch++) {
        __syncthreads();
#pragma unroll
        for (int cc = 0; cc < 16; cc++)
            dyn[t * 17 + cc] = pacc[ch * 16 + cc];
        __syncthreads();
        int rr = t >> 4, cc = t & 15;
        float s = 0.f;
#pragma unroll
        for (int gg = 0; gg < 16; gg++)
            s += dyn[(gg * 16 + rr) * 17 + cc];
        g_dvatt[((long)b * 256 + h * 32 + ch * 16 + cc) * DEMO_TOK + itile * 16 + rr] = s;
    }
}

// ---------------- fused obs attention (round-10 passing version) ----------------
__global__ __launch_bounds__(256, 2) void k_obs_fused(float* __restrict__ part) {
    extern __shared__ float smem[];
    float* Ps = smem;
    float* Qs = smem + 12800;
    float* Kb = smem + 19456;
    float* Vb = smem + 23552;
    const int z = blockIdx.x;
    const int khalf = blockIdx.y;
    const int b = z / 96, tt = (z >> 3) % 12, h = z & 7;
    const int t = threadIdx.x;
    const float* Kd = g_dk    + ((long)b * 256 + h * 32) * DEMO_TOK;
    const float* Ko = g_ok    + ((long)b * 256 + h * 32) * OBS_TOK + tt * 196;
    const float* Vd = g_dvatt + ((long)b * 256 + h * 32) * DEMO_TOK;
    const float* Vo = g_ov    + ((long)b * 256 + h * 32) * OBS_TOK + tt * 196;
    const float* Qp = g_oq    + ((long)b * 256 + h * 32) * OBS_TOK + tt * 196;
    const uint32_t kbs = (uint32_t)__cvta_generic_to_shared(Kb);
    const uint32_t vbs = (uint32_t)__cvta_generic_to_shared(Vb);
    const int kbase = khalf * 490;

    for (int e = t; e < 6272; e += 256) {
        int c = e / 196, j = e - c * 196;
        Qs[c * 208 + (j / 49) * 52 + (j % 49)] = Qp[(long)c * OBS_TOK + j];
    }

#define PREF_K(KT, S) do { \
    _Pragma("unroll") \
    for (int i_ = 0; i_ < 8; i_++) { \
        int e_ = i_ * 256 + t; \
        int c_ = e_ >> 6, ii_ = e_ & 63; \
        int kl_ = (KT) * 64 + ii_; \
        int sz_ = (kl_ < 490) ? 4 : 0; \
        int kg_ = kbase + ((kl_ < 490) ? kl_ : 0); \
        const float* s_ = (kg_ < DEMO_TOK) ? (Kd + (long)c_ * DEMO_TOK + kg_) \
                                           : (Ko + (long)c_ * OBS_TOK + (kg_ - DEMO_TOK)); \
        cp_async4(kbs + (uint32_t)(((S) * 2048 + c_ * 64 + ii_) * 4), s_, sz_); \
    } cp_commit(); } while (0)

#define PREF_VO(KT, S) do { \
    _Pragma("unroll") \
    for (int i_ = 0; i_ < 8; i_++) { \
        int e_ = i_ * 256 + t; \
        int c_ = e_ >> 6, ii_ = e_ & 63; \
        int kl_ = (KT) * 64 + ii_; \
        int sz_ = (kl_ < 490) ? 4 : 0; \
        int kg_ = kbase + ((kl_ < 490) ? kl_ : 0); \
        const float* s_ = (kg_ < DEMO_TOK) ? (Vd + (long)c_ * DEMO_TOK + kg_) \
                                           : (Vo + (long)c_ * OBS_TOK + (kg_ - DEMO_TOK)); \
        cp_async4(vbs + (uint32_t)(((S) * 2304 + ii_ * 36 + c_) * 4), s_, sz_); \
    } cp_commit(); } while (0)

    const int r = t >> 2, gq = t & 3;
    const int w = t >> 5, jg = t & 31;
    const bool has7 = (jg < 4);
    unsigned long long out2[2][7];
#pragma unroll
    for (int cc = 0; cc < 2; cc++)
#pragma unroll
        for (int q = 0; q < 7; q++) out2[cc][q] = 0ull;

    PREF_K(0, 0);
    PREF_VO(0, 0);

    for (int kt = 0; kt < 8; kt++) {
        const int cur = kt & 1;
        if (kt < 7) { PREF_K(kt + 1, cur ^ 1); cp_wait<2>(); }
        else        { cp_wait<1>(); }
        __syncthreads();
        const float* Kc = Kb + cur * 2048;
        unsigned long long acc2[24];
        float acc48 = 0.f;
#pragma unroll
        for (int p = 0; p < 24; p++) acc2[p] = 0ull;
#pragma unroll
        for (int c = 0; c < 32; c++) {
            float a = Kc[c * 64 + r];
            unsigned long long aa = pk2(a);
            const ulonglong2* q2 = (const ulonglong2*)&Qs[c * 208 + gq * 52];
#pragma unroll
            for (int v = 0; v < 12; v++) {
                ulonglong2 qq = q2[v];
                acc2[v*2+0] = fma2(aa, qq.x, acc2[v*2+0]);
                acc2[v*2+1] = fma2(aa, qq.y, acc2[v*2+1]);
            }
            acc48 += a * Qs[c * 208 + gq * 52 + 48];
        }
        float acc[49];
#pragma unroll
        for (int p = 0; p < 24; p++) {
            float2 f = upk(acc2[p]);
            acc[p*2] = f.x; acc[p*2+1] = f.y;
        }
        acc[48] = acc48;
        float mx = -1e30f;
#pragma unroll
        for (int jj = 0; jj < 49; jj++) { acc[jj] *= INV_TEMP; mx = fmaxf(mx, acc[jj]); }
        mx = fmaxf(mx, __shfl_xor_sync(0xffffffffu, mx, 1));
        mx = fmaxf(mx, __shfl_xor_sync(0xffffffffu, mx, 2));
        float sm = 0.f;
#pragma unroll
        for (int jj = 0; jj < 49; jj++) { float p = __expf(acc[jj] - mx); acc[jj] = p; sm += p; }
        sm += __shfl_xor_sync(0xffffffffu, sm, 1);
        sm += __shfl_xor_sync(0xffffffffu, sm, 2);
        float inv = 1.f / sm;
        {
            float* pr = &Ps[r * 200 + gq * 49];
#pragma unroll
            for (int jj = 0; jj < 49; jj++) pr[jj] = acc[jj] * inv;
        }
        if (kt < 7) { PREF_VO(kt + 1, cur ^ 1); cp_wait<2>(); }
        else        { cp_wait<0>(); }
        __syncthreads();
        const float* Vc = Vb + cur * 2304;
#pragma unroll 4
        for (int k = 0; k < 64; k++) {
            ulonglong2 v2 = *(const ulonglong2*)&Vc[k * 36 + w * 4];
            const float* pr = &Ps[k * 200 + jg];
            unsigned long long pp0 = pk2(pr[0]);
            unsigned long long pp1 = pk2(pr[32]);
            unsigned long long pp2 = pk2(pr[64]);
            unsigned long long pp3 = pk2(pr[96]);
            unsigned long long pp4 = pk2(pr[128]);
            unsigned long long pp5 = pk2(pr[160]);
            unsigned long long pp6 = pk2(has7 ? pr[192] : 0.f);
            out2[0][0] = fma2(v2.x, pp0, out2[0][0]); out2[1][0] = fma2(v2.y, pp0, out2[1][0]);
            out2[0][1] = fma2(v2.x, pp1, out2[0][1]); out2[1][1] = fma2(v2.y, pp1, out2[1][1]);
            out2[0][2] = fma2(v2.x, pp2, out2[0][2]); out2[1][2] = fma2(v2.y, pp2, out2[1][2]);
            out2[0][3] = fma2(v2.x, pp3, out2[0][3]); out2[1][3] = fma2(v2.y, pp3, out2[1][3]);
            out2[0][4] = fma2(v2.x, pp4, out2[0][4]); out2[1][4] = fma2(v2.y, pp4, out2[1][4]);
            out2[0][5] = fma2(v2.x, pp5, out2[0][5]); out2[1][5] = fma2(v2.y, pp5, out2[1][5]);
            out2[0][6] = fma2(v2.x, pp6, out2[0][6]); out2[1][6] = fma2(v2.y, pp6, out2[1][6]);
        }
    }
#undef PREF_K
#undef PREF_VO
    float* op = part + ((long)(khalf * 384 + z)) * 6272;
#pragma unroll
    for (int u = 0; u < 2; u++)
#pragma unroll
        for (int q = 0; q < 7; q++) {
            int j = jg + 32 * q;
            if (j < 196) {
                float2 f = upk(out2[u][q]);
                op[(w * 4 + u * 2 + 0) * 196 + j] = f.x;
                op[(w * 4 + u * 2 + 1) * 196 + j] = f.y;
            }
        }
}

__global__ void k_merge(const float* __restrict__ part) {
    int z = blockIdx.y;
    int e = blockIdx.x * 256 + threadIdx.x;
    if (e >= 6272) return;
    int c = e / 196, j = e - c * 196;
    int b = z / 96, tt = (z >> 3) % 12, h = z & 7;
    float v = part[(long)z * 6272 + e] + part[(long)(384 + z) * 6272 + e];
    g_mg[((long)b * 256 + h * 32 + c) * OBS_TOK + tt * 196 + j] = v;
}

__global__ void k_bnstats() {
    const int c = blockIdx.x;
    float s = 0.f, s2 = 0.f;
    for (int e = threadIdx.x; e < BB * THW; e += 256) {
        int b = e / THW, k = e - b * THW;
        float v = g_x[(long)b * CTHW + (long)c * THW + k];
        s += v; s2 += v * v;
    }
#pragma unroll
    for (int o = 16; o; o >>= 1) {
        s  += __shfl_xor_sync(0xffffffffu, s, o);
        s2 += __shfl_xor_sync(0xffffffffu, s2, o);
    }
    __shared__ float ws[8], ws2[8];
    int w = threadIdx.x >> 5;
    if ((threadIdx.x & 31) == 0) { ws[w] = s; ws2[w] = s2; }
    __syncthreads();
    if (threadIdx.x == 0) {
        float S = 0.f, S2 = 0.f;
#pragma unroll
        for (int i = 0; i < 8; i++) { S += ws[i]; S2 += ws2[i]; }
        float m = S * (1.f / 12544.f);
        float var = S2 * (1.f / 12544.f) - m * m;
        g_mean[c] = m;
        g_istd[c] = rsqrtf(var + EPSV);
    }
}

__global__ void k_bnapply(const float* __restrict__ gamma, const float* __restrict__ beta,
                          float* __restrict__ out) {
    int e = blockIdx.x * 256 + threadIdx.x;
    int c = (e / 784) & 255;
    float4 v = ((const float4*)g_x)[e];
    float a = gamma[c] * g_istd[c];
    float b2 = beta[c] - g_mean[c] * a;
    v.x = v.x * a + b2; v.y = v.y * a + b2; v.z = v.z * a + b2; v.w = v.w * a + b2;
    ((float4*)out)[e] = v;
}

extern "C" void kernel_launch(void* const* d_in, const int* in_sizes, int n_in,
                              void* d_out, int out_size) {
    const float* x    = (const float*)d_in[0];
    const float* w_dq = (const float*)d_in[1];
    const float* w_dk = (const float*)d_in[2];
    const float* w_dv = (const float*)d_in[3];
    const float* w_oq = (const float*)d_in[4];
    const float* w_ok = (const float*)d_in[5];
    const float* w_ov = (const float*)d_in[6];
    const float* w_oo = (const float*)d_in[7];
    const float* gam  = (const float*)d_in[8];
    const float* bet  = (const float*)d_in[9];
    float* out = (float*)d_out;

    float *p_x, *p_part;
    cudaGetSymbolAddress((void**)&p_x, g_x);
    cudaGetSymbolAddress((void**)&p_part, g_part);

    cudaFuncSetAttribute(k_obs_fused, cudaFuncAttributeMaxDynamicSharedMemorySize, 112640);
    cudaFuncSetAttribute(k_demo_fused, cudaFuncAttributeMaxDynamicSharedMemorySize, 59904);

    k_copy<<<3136, 256>>>((const float4*)x);

    for (int l = 0; l < 3; l++) {
        const int WO = l * 256 * 256;
        k_convD<<<dim3(13, 12, BB), 256>>>(w_dq + WO, w_dk + WO, w_dv + WO);
        k_convB<<<dim3(37, 12, BB), 256>>>(w_oq + WO, w_ok + WO, w_ov + WO);
        k_demo_fused<<<dim3(49, 32), 256, 59904>>>();
        k_obs_fused<<<dim3(384, 2), 256, 112640>>>(p_part);
        k_merge<<<dim3(25, 384), 256>>>(p_part);
        k_convO<<<dim3(37, 4, BB), 256>>>(w_oo + WO);
        k_bnstats<<<256, 256>>>();
        k_bnapply<<<3136, 256>>>(gam + l * 256, bet + l * 256, (l == 2) ? out : p_x);
    }
}